// round 6
// baseline (speedup 1.0000x reference)
#include <cuda_runtime.h>
#include <cuda_fp16.h>
#include <cstdint>
#include <math.h>

// Problem constants
#define TT 2048
#define DD 4096
#define NH 32
#define KH 8
#define HD 128
#define SCALE 0.08838834764831843f   // 1/sqrt(128)

// ====================== PTX helpers (base sm_103-legal only) ======================
__device__ __forceinline__ uint32_t smem_to_u32(const void* p) {
    uint32_t a;
    asm("{ .reg .u64 t; cvta.to.shared.u64 t, %1; cvt.u32.u64 %0, t; }" : "=r"(a) : "l"(p));
    return a;
}
#define CP16(sa, ga) \
    asm volatile("cp.async.cg.shared.global [%0], [%1], 16;" :: "r"(sa), "l"(ga) : "memory")
#define CP_COMMIT() asm volatile("cp.async.commit_group;" ::: "memory")
#define CP_WAIT(n)  asm volatile("cp.async.wait_group %0;" :: "n"(n) : "memory")
#define LDSM4(r, a) \
    asm volatile("ldmatrix.sync.aligned.m8n8.x4.shared.b16 {%0,%1,%2,%3}, [%4];" \
        : "=r"((r)[0]), "=r"((r)[1]), "=r"((r)[2]), "=r"((r)[3]) : "r"(a))
#define LDSM2(r, a) \
    asm volatile("ldmatrix.sync.aligned.m8n8.x2.shared.b16 {%0,%1}, [%2];" \
        : "=r"((r)[0]), "=r"((r)[1]) : "r"(a))
#define LDSM2T(r, a) \
    asm volatile("ldmatrix.sync.aligned.m8n8.x2.trans.shared.b16 {%0,%1}, [%2];" \
        : "=r"((r)[0]), "=r"((r)[1]) : "r"(a))
#define MMAH(d, a, b) \
    asm volatile("mma.sync.aligned.m16n8k16.row.col.f32.f16.f16.f32 " \
        "{%0,%1,%2,%3}, {%4,%5,%6,%7}, {%8,%9}, {%0,%1,%2,%3};" \
        : "+f"((d)[0]), "+f"((d)[1]), "+f"((d)[2]), "+f"((d)[3]) \
        : "r"((a)[0]), "r"((a)[1]), "r"((a)[2]), "r"((a)[3]), "r"((b)[0]), "r"((b)[1]))

// ====================== device scratch ======================
__device__ float  g_q [TT * NH * HD];
__device__ float  g_k [TT * KH * HD];
__device__ float  g_v [TT * KH * HD];

__device__ __half g_xh [TT * DD],  g_xl [TT * DD];
__device__ __half g_aoh[TT * DD],  g_aol[TT * DD];
__device__ __half g_wqT[DD * DD];                 // transposed [N][K] fp16
__device__ __half g_wkT[KH*HD * DD];
__device__ __half g_wvT[KH*HD * DD];
__device__ __half g_woT[DD * DD];
__device__ __half g_qh [TT * NH * HD], g_ql [TT * NH * HD];
__device__ __half g_kh [TT * KH * HD];
__device__ __half g_vh [TT * KH * HD];

// ====================== fp32 -> fp16 hi/lo split ======================
__global__ void split_f32h(const float* __restrict__ s, __half* __restrict__ hi,
                           __half* __restrict__ lo, int n4)
{
    int i = blockIdx.x * 256 + threadIdx.x;
    if (i >= n4) return;
    float4 f = ((const float4*)s)[i];
    float v[4] = {f.x, f.y, f.z, f.w};
    __align__(8) __half h[4], l[4];
    #pragma unroll
    for (int j = 0; j < 4; j++) {
        h[j] = __float2half_rn(v[j]);
        l[j] = __float2half_rn(v[j] - __half2float(h[j]));
    }
    *(uint2*)(hi + 4 * (size_t)i) = *(uint2*)h;
    *(uint2*)(lo + 4 * (size_t)i) = *(uint2*)l;
}

// transpose fp32 [R,C] -> single fp16 [C,R]
__global__ __launch_bounds__(256) void transT_f16(const float* __restrict__ s,
    __half* __restrict__ d, int R, int C)
{
    __shared__ float t[32][33];
    int bx = blockIdx.x * 32, by = blockIdx.y * 32;
    int tx = threadIdx.x & 31, ty = threadIdx.x >> 5;
    #pragma unroll
    for (int j = 0; j < 4; j++)
        t[ty + 8*j][tx] = s[(size_t)(by + ty + 8*j) * C + bx + tx];
    __syncthreads();
    #pragma unroll
    for (int j = 0; j < 4; j++)
        d[(size_t)(bx + ty + 8*j) * R + by + tx] = __float2half_rn(t[tx][ty + 8*j]);
}

// ====================== mma.sync fp16x2 GEMM, 128x256 tile ======================
// C[M,N] = (Ahi+Alo)[M,K] x BT[N,K]^T.  BK=32, 8 warps (2x4), warp tile 64x64.
#define SROWB 80                        // smem row stride bytes (32 halves + pad)
#define A_TILE (128 * SROWB)            // 10240
#define B_TILE (256 * SROWB)            // 20480
#define B_OFF  (2 * A_TILE)             // Ahi | Alo | B
#define STAGE_B (2 * A_TILE + B_TILE)   // 40960
#define GEMM_SMEM (2 * STAGE_B)         // 81920

__global__ __launch_bounds__(256, 1) void gemm_fh2(
    const __half* __restrict__ Ahi, const __half* __restrict__ Alo,
    const __half* __restrict__ BT, float* __restrict__ C, int M, int N, int Kd)
{
    extern __shared__ char smraw[];
    const uint32_t sbase = smem_to_u32(smraw);
    const int tid = threadIdx.x, lane = tid & 31, wid = tid >> 5;
    const int wm = wid >> 2, wn = wid & 3;

    const __half* pAh = Ahi + (size_t)blockIdx.y * 128 * Kd;
    const __half* pAl = Alo + (size_t)blockIdx.y * 128 * Kd;
    const __half* pB  = BT  + (size_t)blockIdx.x * 256 * Kd;

    float acc[4][8][4];
    #pragma unroll
    for (int mt = 0; mt < 4; mt++)
        #pragma unroll
        for (int nt = 0; nt < 8; nt++)
            #pragma unroll
            for (int q = 0; q < 4; q++) acc[mt][nt][q] = 0.f;

    const int nst = Kd >> 5;

    // loaders: A 128 rows x 4 chunks (2/thread), B 256 rows x 4 chunks (4/thread)
    {   // prologue stage 0
        #pragma unroll
        for (int i = 0; i < 2; i++) {
            int c = tid + 256 * i, row = c >> 2;
            uint32_t so = sbase + (uint32_t)row * SROWB + (c & 3) * 16;
            size_t go = (size_t)row * Kd + (c & 3) * 8;
            CP16(so,          pAh + go);
            CP16(so + A_TILE, pAl + go);
        }
        #pragma unroll
        for (int i = 0; i < 4; i++) {
            int c = tid + 256 * i, row = c >> 2;
            CP16(sbase + B_OFF + (uint32_t)row * SROWB + (c & 3) * 16,
                 pB + (size_t)row * Kd + (c & 3) * 8);
        }
        CP_COMMIT();
    }

    for (int s = 0; s < nst; s++) {
        if (s + 1 < nst) {
            const int k0 = (s + 1) << 5;
            uint32_t st = sbase + ((s + 1) & 1) * STAGE_B;
            #pragma unroll
            for (int i = 0; i < 2; i++) {
                int c = tid + 256 * i, row = c >> 2;
                uint32_t so = st + (uint32_t)row * SROWB + (c & 3) * 16;
                size_t go = (size_t)row * Kd + k0 + (c & 3) * 8;
                CP16(so,          pAh + go);
                CP16(so + A_TILE, pAl + go);
            }
            #pragma unroll
            for (int i = 0; i < 4; i++) {
                int c = tid + 256 * i, row = c >> 2;
                CP16(st + B_OFF + (uint32_t)row * SROWB + (c & 3) * 16,
                     pB + (size_t)row * Kd + k0 + (c & 3) * 8);
            }
            CP_COMMIT();
            CP_WAIT(1);
        } else {
            CP_WAIT(0);
        }
        __syncthreads();

        uint32_t st = sbase + (s & 1) * STAGE_B;
        const uint32_t aAddr = st + (uint32_t)(wm * 64 + (lane & 15)) * SROWB
                             + (lane >> 4) * 16;
        const uint32_t bAddr = st + B_OFF
                             + (uint32_t)(wn * 64 + (lane & 7)) * SROWB
                             + ((lane >> 3) & 1) * 16;

        #pragma unroll
        for (int kk = 0; kk < 2; kk++) {
            uint32_t ah[4][4], al[4][4], bb[8][2];
            #pragma unroll
            for (int mt = 0; mt < 4; mt++)
                LDSM4(ah[mt], aAddr + mt * 16 * SROWB + kk * 32);
            #pragma unroll
            for (int nt = 0; nt < 8; nt++)
                LDSM2(bb[nt], bAddr + nt * 8 * SROWB + kk * 32);
            #pragma unroll
            for (int mt = 0; mt < 4; mt++)
                #pragma unroll
                for (int nt = 0; nt < 8; nt++)
                    MMAH(acc[mt][nt], ah[mt], bb[nt]);          // Ahi * B
            #pragma unroll
            for (int mt = 0; mt < 4; mt++)
                LDSM4(al[mt], aAddr + A_TILE + mt * 16 * SROWB + kk * 32);
            #pragma unroll
            for (int mt = 0; mt < 4; mt++)
                #pragma unroll
                for (int nt = 0; nt < 8; nt++)
                    MMAH(acc[mt][nt], al[mt], bb[nt]);          // Alo * B
        }
        __syncthreads();
    }

    const int rb = blockIdx.y * 128 + wm * 64 + (lane >> 2);
    const int cb = blockIdx.x * 256 + wn * 64 + (lane & 3) * 2;
    #pragma unroll
    for (int mt = 0; mt < 4; mt++)
        #pragma unroll
        for (int nt = 0; nt < 8; nt++) {
            const int row = rb + mt * 16;
            const int col = cb + nt * 8;
            *(float2*)(C + (size_t)row * N + col) =
                make_float2(acc[mt][nt][0], acc[mt][nt][1]);
            *(float2*)(C + (size_t)(row + 8) * N + col) =
                make_float2(acc[mt][nt][2], acc[mt][nt][3]);
        }
}

// ====================== RoPE + fp16 outputs ======================
__global__ void rope_q(const float* __restrict__ src, const int* __restrict__ pos,
                       __half* __restrict__ qh, __half* __restrict__ ql)
{
    int idx = blockIdx.x * 256 + threadIdx.x;
    if (idx >= TT * NH * 64) return;
    int hh = idx & 63;
    int h  = (idx >> 6) % NH;
    int t  = idx / (64 * NH);

    float e   = (float)hh * (1.0f / 64.0f);
    float inv = 1.0f / powf(10000.0f, e);
    float ang = (float)pos[t] * inv;
    float s, c;
    sincosf(ang, &s, &c);

    size_t base = ((size_t)t * NH + h) * HD + hh;
    float x1 = src[base], x2 = src[base + 64];
    float y1 = (x1 * c - x2 * s) * SCALE;
    float y2 = (x2 * c + x1 * s) * SCALE;
    __half h1 = __float2half_rn(y1), h2 = __float2half_rn(y2);
    qh[base]      = h1;  ql[base]      = __float2half_rn(y1 - __half2float(h1));
    qh[base + 64] = h2;  ql[base + 64] = __float2half_rn(y2 - __half2float(h2));
}

__global__ void rope_k(const float* __restrict__ src, const int* __restrict__ pos,
                       __half* __restrict__ kh)
{
    int idx = blockIdx.x * 256 + threadIdx.x;
    if (idx >= TT * KH * 64) return;
    int hh = idx & 63;
    int h  = (idx >> 6) % KH;
    int t  = idx / (64 * KH);

    float e   = (float)hh * (1.0f / 64.0f);
    float inv = 1.0f / powf(10000.0f, e);
    float ang = (float)pos[t] * inv;
    float s, c;
    sincosf(ang, &s, &c);

    size_t base = ((size_t)t * KH + h) * HD + hh;
    float x1 = src[base], x2 = src[base + 64];
    kh[base]      = __float2half_rn(x1 * c - x2 * s);
    kh[base + 64] = __float2half_rn(x2 * c + x1 * s);
}

__global__ void conv_h(const float* __restrict__ s, __half* __restrict__ d, int n4)
{
    int i = blockIdx.x * 256 + threadIdx.x;
    if (i >= n4) return;
    float4 f = ((const float4*)s)[i];
    __align__(8) __half h[4] = {__float2half_rn(f.x), __float2half_rn(f.y),
                                __float2half_rn(f.z), __float2half_rn(f.w)};
    *(uint2*)(d + 4 * (size_t)i) = *(uint2*)h;
}

// ====================== HMMA flash attention (causal, GQA) ======================
// CTA: 128 q rows x 1 head, 8 warps (16 q rows each). KV tiles of 64.
#define SRH 136
#define SRB 272
#define FL_SMEM ((128 * SRH + 4 * 64 * SRH) * 2)   // Qlo + 2 stages of (K,V)

__global__ __launch_bounds__(256) void flash_h(
    const __half* __restrict__ Qhi, const __half* __restrict__ Qlo,
    const __half* __restrict__ Kv,  const __half* __restrict__ Vv,
    __half* __restrict__ Oh, __half* __restrict__ Ol)
{
    extern __shared__ char fsm[];
    const uint32_t uQlo = smem_to_u32(fsm);
    const uint32_t uSt  = uQlo + 128 * SRB;

    const int tid = threadIdx.x, lane = tid & 31, wid = tid >> 5;
    const int qi = blockIdx.x, n = blockIdx.y, kvh = n >> 2;
    const int tq0 = qi * 128;
    const int ntiles = 2 * qi + 2;

    const __half* Qhg = Qhi + ((size_t)tq0 * NH + n) * HD;
    const __half* Qlg = Qlo + ((size_t)tq0 * NH + n) * HD;
    const __half* Kg  = Kv + (size_t)kvh * HD;
    const __half* Vg  = Vv + (size_t)kvh * HD;

    // ---- stage Qhi (into stage area) + Qlo (persistent) ----
    #pragma unroll
    for (int i = 0; i < 8; i++) {
        int c = tid + 256 * i;
        int row = c >> 4, c16 = c & 15;
        size_t go = (size_t)row * (NH * HD) + c16 * 8;
        CP16(uSt  + (uint32_t)row * SRB + c16 * 16, Qhg + go);
        CP16(uQlo + (uint32_t)row * SRB + c16 * 16, Qlg + go);
    }
    CP_COMMIT();
    CP_WAIT(0);
    __syncthreads();

    uint32_t qh[8][4];
    {
        const uint32_t qa = uSt + (uint32_t)(wid * 16 + (lane & 15)) * SRB
                          + (lane >> 4) * 16;
        #pragma unroll
        for (int dc = 0; dc < 8; dc++)
            LDSM4(qh[dc], qa + dc * 32);
    }
    __syncthreads();   // stage area free for KV

    const uint32_t qlA = uQlo + (uint32_t)(wid * 16 + (lane & 15)) * SRB
                       + (lane >> 4) * 16;
    const int l8 = lane & 7, ls8 = (lane >> 3) & 1;

    float o[16][4];
    #pragma unroll
    for (int i = 0; i < 16; i++)
        #pragma unroll
        for (int j = 0; j < 4; j++) o[i][j] = 0.f;
    float m0 = -1e30f, m1 = -1e30f, l0 = 0.f, l1 = 0.f;

    // preload tile 0
    #pragma unroll
    for (int i = 0; i < 4; i++) {
        int c = tid + 256 * i;
        int row = c >> 4, c16 = c & 15;
        size_t go = (size_t)row * (KH * HD) + c16 * 8;
        CP16(uSt + (uint32_t)row * SRB + c16 * 16, Kg + go);
        CP16(uSt + 64 * SRB + (uint32_t)row * SRB + c16 * 16, Vg + go);
    }
    CP_COMMIT();

    for (int t = 0; t < ntiles; t++) {
        if (t + 1 < ntiles) {
            uint32_t st = uSt + ((t + 1) & 1) * (2 * 64 * SRB);
            const int s0 = (t + 1) * 64;
            #pragma unroll
            for (int i = 0; i < 4; i++) {
                int c = tid + 256 * i;
                int row = c >> 4, c16 = c & 15;
                size_t go = (size_t)(s0 + row) * (KH * HD) + c16 * 8;
                CP16(st + (uint32_t)row * SRB + c16 * 16, Kg + go);
                CP16(st + 64 * SRB + (uint32_t)row * SRB + c16 * 16, Vg + go);
            }
            CP_COMMIT();
            CP_WAIT(1);
        } else {
            CP_WAIT(0);
        }
        __syncthreads();

        const uint32_t uK = uSt + (t & 1) * (2 * 64 * SRB);
        const uint32_t uV = uK + 64 * SRB;

        // ---- S = Q K^T ----  (K smem is [token][dim] == [N,K]: NON-trans B load)
        float s[8][4];
        #pragma unroll
        for (int nt = 0; nt < 8; nt++)
            #pragma unroll
            for (int j = 0; j < 4; j++) s[nt][j] = 0.f;

        #pragma unroll
        for (int dc = 0; dc < 8; dc++) {
            uint32_t ql[4];
            LDSM4(ql, qlA + dc * 32);
            #pragma unroll
            for (int nt = 0; nt < 8; nt++) {
                uint32_t bb[2];
                LDSM2(bb, uK + (uint32_t)(nt * 8 + l8) * SRB + (dc * 16 + ls8 * 8) * 2);
                MMAH(s[nt], qh[dc], bb);
                MMAH(s[nt], ql, bb);
            }
        }

        // ---- causal mask ----
        if (t >= 2 * qi) {
            const int r0 = tq0 + wid * 16 + (lane >> 2);
            const int cB = t * 64 + (lane & 3) * 2;
            #pragma unroll
            for (int nt = 0; nt < 8; nt++) {
                int c0 = cB + nt * 8;
                if (c0     > r0)     s[nt][0] = -1e30f;
                if (c0 + 1 > r0)     s[nt][1] = -1e30f;
                if (c0     > r0 + 8) s[nt][2] = -1e30f;
                if (c0 + 1 > r0 + 8) s[nt][3] = -1e30f;
            }
        }

        // ---- online softmax ----
        float mr0 = -1e30f, mr1 = -1e30f;
        #pragma unroll
        for (int nt = 0; nt < 8; nt++) {
            mr0 = fmaxf(mr0, fmaxf(s[nt][0], s[nt][1]));
            mr1 = fmaxf(mr1, fmaxf(s[nt][2], s[nt][3]));
        }
        mr0 = fmaxf(mr0, __shfl_xor_sync(0xffffffffu, mr0, 1));
        mr0 = fmaxf(mr0, __shfl_xor_sync(0xffffffffu, mr0, 2));
        mr1 = fmaxf(mr1, __shfl_xor_sync(0xffffffffu, mr1, 1));
        mr1 = fmaxf(mr1, __shfl_xor_sync(0xffffffffu, mr1, 2));

        const float mn0 = fmaxf(m0, mr0), mn1 = fmaxf(m1, mr1);
        const float a0 = __expf(m0 - mn0), a1 = __expf(m1 - mn1);
        m0 = mn0; m1 = mn1;

        float ls0 = 0.f, ls1 = 0.f;
        #pragma unroll
        for (int nt = 0; nt < 8; nt++) {
            s[nt][0] = __expf(s[nt][0] - m0); ls0 += s[nt][0];
            s[nt][1] = __expf(s[nt][1] - m0); ls0 += s[nt][1];
            s[nt][2] = __expf(s[nt][2] - m1); ls1 += s[nt][2];
            s[nt][3] = __expf(s[nt][3] - m1); ls1 += s[nt][3];
        }
        ls0 += __shfl_xor_sync(0xffffffffu, ls0, 1);
        ls0 += __shfl_xor_sync(0xffffffffu, ls0, 2);
        ls1 += __shfl_xor_sync(0xffffffffu, ls1, 1);
        ls1 += __shfl_xor_sync(0xffffffffu, ls1, 2);
        l0 = l0 * a0 + ls0;
        l1 = l1 * a1 + ls1;

        #pragma unroll
        for (int i = 0; i < 16; i++) {
            o[i][0] *= a0; o[i][1] *= a0; o[i][2] *= a1; o[i][3] *= a1;
        }

        // ---- P fragments (hi/lo fp16) ----
        uint32_t phi[4][4], plo[4][4];
        #pragma unroll
        for (int kc = 0; kc < 4; kc++) {
            #pragma unroll
            for (int q = 0; q < 4; q++) {
                int nt = 2 * kc + (q >> 1);
                float f0 = s[nt][(q & 1) * 2], f1 = s[nt][(q & 1) * 2 + 1];
                __half2 h = __floats2half2_rn(f0, f1);
                float2 hf = __half22float2(h);
                __half2 l = __floats2half2_rn(f0 - hf.x, f1 - hf.y);
                phi[kc][q] = *(uint32_t*)&h;
                plo[kc][q] = *(uint32_t*)&l;
            }
        }

        // ---- O += P V ----  (V smem is [token=k][dim=n]: trans B load)
        #pragma unroll
        for (int nt2 = 0; nt2 < 16; nt2++) {
            #pragma unroll
            for (int kc = 0; kc < 4; kc++) {
                uint32_t bb[2];
                LDSM2T(bb, uV + (uint32_t)(kc * 16 + ls8 * 8 + l8) * SRB + nt2 * 16);
                MMAH(o[nt2], phi[kc], bb);
                MMAH(o[nt2], plo[kc], bb);
            }
        }
        __syncthreads();
    }

    // ---- epilogue: O / l, write fp16 hi/lo ----
    const float i0 = 1.f / l0, i1 = 1.f / l1;
    const int r0 = tq0 + wid * 16 + (lane >> 2);
    const int cofs = (lane & 3) * 2;
    #pragma unroll
    for (int nt2 = 0; nt2 < 16; nt2++) {
        float v0 = o[nt2][0] * i0, v1 = o[nt2][1] * i0;
        float v2 = o[nt2][2] * i1, v3 = o[nt2][3] * i1;
        size_t p0 = ((size_t)r0 * NH + n) * HD + nt2 * 8 + cofs;
        size_t p1 = ((size_t)(r0 + 8) * NH + n) * HD + nt2 * 8 + cofs;
        __half2 h0 = __floats2half2_rn(v0, v1);
        float2 hf0 = __half22float2(h0);
        __half2 l0h = __floats2half2_rn(v0 - hf0.x, v1 - hf0.y);
        __half2 h1 = __floats2half2_rn(v2, v3);
        float2 hf1 = __half22float2(h1);
        __half2 l1h = __floats2half2_rn(v2 - hf1.x, v3 - hf1.y);
        *(__half2*)(Oh + p0) = h0;  *(__half2*)(Ol + p0) = l0h;
        *(__half2*)(Oh + p1) = h1;  *(__half2*)(Ol + p1) = l1h;
    }
}

// ====================== launch ======================
extern "C" void kernel_launch(void* const* d_in, const int* in_sizes, int n_in,
                              void* d_out, int out_size)
{
    const float* x   = (const float*)d_in[0];
    const int*   pos = (const int*)  d_in[1];
    const float* w_q = (const float*)d_in[2];
    const float* w_k = (const float*)d_in[3];
    const float* w_v = (const float*)d_in[4];
    const float* w_o = (const float*)d_in[5];
    float* out = (float*)d_out;

    float *q, *k, *v;
    cudaGetSymbolAddress((void**)&q, g_q);
    cudaGetSymbolAddress((void**)&k, g_k);
    cudaGetSymbolAddress((void**)&v, g_v);
    __half *xh, *xl, *aoh, *aol, *wqT, *wkT, *wvT, *woT, *qh, *ql, *kh, *vh;
    cudaGetSymbolAddress((void**)&xh,  g_xh);  cudaGetSymbolAddress((void**)&xl,  g_xl);
    cudaGetSymbolAddress((void**)&aoh, g_aoh); cudaGetSymbolAddress((void**)&aol, g_aol);
    cudaGetSymbolAddress((void**)&wqT, g_wqT); cudaGetSymbolAddress((void**)&wkT, g_wkT);
    cudaGetSymbolAddress((void**)&wvT, g_wvT); cudaGetSymbolAddress((void**)&woT, g_woT);
    cudaGetSymbolAddress((void**)&qh,  g_qh);  cudaGetSymbolAddress((void**)&ql,  g_ql);
    cudaGetSymbolAddress((void**)&kh,  g_kh);  cudaGetSymbolAddress((void**)&vh,  g_vh);

    cudaFuncSetAttribute(gemm_fh2, cudaFuncAttributeMaxDynamicSharedMemorySize, GEMM_SMEM);
    cudaFuncSetAttribute(flash_h,  cudaFuncAttributeMaxDynamicSharedMemorySize, FL_SMEM);

    // operand prep
    split_f32h<<<(TT*DD/4 + 255)/256, 256>>>(x, xh, xl, TT*DD/4);
    transT_f16<<<dim3(DD/32, DD/32),    256>>>(w_q, wqT, DD, DD);
    transT_f16<<<dim3(KH*HD/32, DD/32), 256>>>(w_k, wkT, DD, KH*HD);
    transT_f16<<<dim3(KH*HD/32, DD/32), 256>>>(w_v, wvT, DD, KH*HD);
    transT_f16<<<dim3(DD/32, DD/32),    256>>>(w_o, woT, DD, DD);

    // QKV projections (N-tile = 256)
    gemm_fh2<<<dim3(16, 16), 256, GEMM_SMEM>>>(xh, xl, wqT, q, TT, NH*HD, DD);
    gemm_fh2<<<dim3(4, 16),  256, GEMM_SMEM>>>(xh, xl, wkT, k, TT, KH*HD, DD);
    gemm_fh2<<<dim3(4, 16),  256, GEMM_SMEM>>>(xh, xl, wvT, v, TT, KH*HD, DD);

    // RoPE + fp16 conversions
    rope_q<<<(TT*NH*64 + 255)/256, 256>>>(q, pos, qh, ql);
    rope_k<<<(TT*KH*64 + 255)/256, 256>>>(k, pos, kh);
    conv_h<<<(TT*KH*HD/4 + 255)/256, 256>>>(v, vh, TT*KH*HD/4);

    // causal GQA flash attention (HMMA) -> fp16 hi/lo attention output
    flash_h<<<dim3(TT/128, NH), 256, FL_SMEM>>>(qh, ql, kh, vh, aoh, aol);

    // output projection
    gemm_fh2<<<dim3(16, 16), 256, GEMM_SMEM>>>(aoh, aol, woT, out, TT, DD, DD);
}

// round 7
// speedup vs baseline: 1.0795x; 1.0795x over previous
#include <cuda_runtime.h>
#include <cuda_fp16.h>
#include <cstdint>
#include <math.h>

// Problem constants
#define TT 2048
#define DD 4096
#define NH 32
#define KH 8
#define HD 128
#define SCALE 0.08838834764831843f   // 1/sqrt(128)

// ====================== PTX helpers (base sm_103-legal only) ======================
__device__ __forceinline__ uint32_t smem_to_u32(const void* p) {
    uint32_t a;
    asm("{ .reg .u64 t; cvta.to.shared.u64 t, %1; cvt.u32.u64 %0, t; }" : "=r"(a) : "l"(p));
    return a;
}
#define CP16(sa, ga) \
    asm volatile("cp.async.cg.shared.global [%0], [%1], 16;" :: "r"(sa), "l"(ga) : "memory")
#define CP_COMMIT() asm volatile("cp.async.commit_group;" ::: "memory")
#define CP_WAIT(n)  asm volatile("cp.async.wait_group %0;" :: "n"(n) : "memory")
#define LDSM4(r, a) \
    asm volatile("ldmatrix.sync.aligned.m8n8.x4.shared.b16 {%0,%1,%2,%3}, [%4];" \
        : "=r"((r)[0]), "=r"((r)[1]), "=r"((r)[2]), "=r"((r)[3]) : "r"(a))
#define LDSM2(r, a) \
    asm volatile("ldmatrix.sync.aligned.m8n8.x2.shared.b16 {%0,%1}, [%2];" \
        : "=r"((r)[0]), "=r"((r)[1]) : "r"(a))
#define LDSM2T(r, a) \
    asm volatile("ldmatrix.sync.aligned.m8n8.x2.trans.shared.b16 {%0,%1}, [%2];" \
        : "=r"((r)[0]), "=r"((r)[1]) : "r"(a))
#define MMAH(d, a, b) \
    asm volatile("mma.sync.aligned.m16n8k16.row.col.f32.f16.f16.f32 " \
        "{%0,%1,%2,%3}, {%4,%5,%6,%7}, {%8,%9}, {%0,%1,%2,%3};" \
        : "+f"((d)[0]), "+f"((d)[1]), "+f"((d)[2]), "+f"((d)[3]) \
        : "r"((a)[0]), "r"((a)[1]), "r"((a)[2]), "r"((a)[3]), "r"((b)[0]), "r"((b)[1]))

// ====================== device scratch ======================
__device__ float  g_q [TT * NH * HD];
__device__ float  g_k [TT * KH * HD];

__device__ __half g_xh [TT * DD],  g_xl [TT * DD];
__device__ __half g_aoh[TT * DD],  g_aol[TT * DD];
__device__ __half g_wqT[DD * DD];                 // transposed [N][K] fp16
__device__ __half g_wkT[KH*HD * DD];
__device__ __half g_wvT[KH*HD * DD];
__device__ __half g_woT[DD * DD];
__device__ __half g_qh [TT * NH * HD], g_ql [TT * NH * HD];
__device__ __half g_kh [TT * KH * HD];
__device__ __half g_vh [TT * KH * HD];

// ====================== fp32 -> fp16 hi/lo split ======================
__global__ void split_f32h(const float* __restrict__ s, __half* __restrict__ hi,
                           __half* __restrict__ lo, int n4)
{
    int i = blockIdx.x * 256 + threadIdx.x;
    if (i >= n4) return;
    float4 f = ((const float4*)s)[i];
    float v[4] = {f.x, f.y, f.z, f.w};
    __align__(8) __half h[4], l[4];
    #pragma unroll
    for (int j = 0; j < 4; j++) {
        h[j] = __float2half_rn(v[j]);
        l[j] = __float2half_rn(v[j] - __half2float(h[j]));
    }
    *(uint2*)(hi + 4 * (size_t)i) = *(uint2*)h;
    *(uint2*)(lo + 4 * (size_t)i) = *(uint2*)l;
}

// transpose fp32 [R,C] -> single fp16 [C,R]
__global__ __launch_bounds__(256) void transT_f16(const float* __restrict__ s,
    __half* __restrict__ d, int R, int C)
{
    __shared__ float t[32][33];
    int bx = blockIdx.x * 32, by = blockIdx.y * 32;
    int tx = threadIdx.x & 31, ty = threadIdx.x >> 5;
    #pragma unroll
    for (int j = 0; j < 4; j++)
        t[ty + 8*j][tx] = s[(size_t)(by + ty + 8*j) * C + bx + tx];
    __syncthreads();
    #pragma unroll
    for (int j = 0; j < 4; j++)
        d[(size_t)(bx + ty + 8*j) * R + by + tx] = __float2half_rn(t[tx][ty + 8*j]);
}

// ====================== mma.sync fp16x2 GEMM, 128x128 tile, 3-stage ======================
// C[M,N] = (Ahi+Alo)[M,K] x BT[N,K]^T. BK=32, 8 warps (2x4), warp tile 64x32.
#define SROWB 80                       // smem row stride bytes (32 halves + pad)
#define TILE_B (128 * SROWB)           // 10240
#define STAGE_B (3 * TILE_B)           // Ahi | Alo | B   = 30720
#define GEMM_SMEM (3 * STAGE_B)        // 92160 (3 stages)

template <int OUTH>
__global__ __launch_bounds__(256) void gemm_fh2(
    const __half* __restrict__ Ahi, const __half* __restrict__ Alo,
    const __half* __restrict__ BT, void* __restrict__ Cv, int M, int N, int Kd)
{
    extern __shared__ char smraw[];
    const uint32_t sbase = smem_to_u32(smraw);
    const int tid = threadIdx.x, lane = tid & 31, wid = tid >> 5;
    const int wm = wid >> 2, wn = wid & 3;

    const __half* pAh = Ahi + (size_t)blockIdx.y * 128 * Kd;
    const __half* pAl = Alo + (size_t)blockIdx.y * 128 * Kd;
    const __half* pB  = BT  + (size_t)blockIdx.x * 128 * Kd;

    const int lrow  = tid >> 2;
    const int lcolh = (tid & 3) * 8;
    const uint32_t lso = (tid & 3) * 16;

    float acc[4][4][4];
    #pragma unroll
    for (int mt = 0; mt < 4; mt++)
        #pragma unroll
        for (int nt = 0; nt < 4; nt++)
            #pragma unroll
            for (int q = 0; q < 4; q++) acc[mt][nt][q] = 0.f;

    const int nst = Kd >> 5;

    // prologue: stages 0 and 1
    #pragma unroll
    for (int ps = 0; ps < 2; ps++) {
        const int k0 = ps << 5;
        uint32_t st = sbase + ps * STAGE_B;
        #pragma unroll
        for (int i = 0; i < 2; i++) {
            int row = lrow + 64 * i;
            uint32_t so = st + (uint32_t)row * SROWB + lso;
            size_t go = (size_t)row * Kd + k0 + lcolh;
            CP16(so,            pAh + go);
            CP16(so + TILE_B,   pAl + go);
            CP16(so + 2*TILE_B, pB  + go);
        }
        CP_COMMIT();
    }

    int sidx = 0;                       // stage index of s, cycles 0,1,2
    for (int s = 0; s < nst; s++) {
        if (s + 2 < nst) {
            const int k0 = (s + 2) << 5;
            int lidx = sidx - 1; if (lidx < 0) lidx += 3;   // (s+2)%3
            uint32_t st = sbase + lidx * STAGE_B;
            #pragma unroll
            for (int i = 0; i < 2; i++) {
                int row = lrow + 64 * i;
                uint32_t so = st + (uint32_t)row * SROWB + lso;
                size_t go = (size_t)row * Kd + k0 + lcolh;
                CP16(so,            pAh + go);
                CP16(so + TILE_B,   pAl + go);
                CP16(so + 2*TILE_B, pB  + go);
            }
            CP_COMMIT();
            CP_WAIT(2);
        } else if (s + 1 < nst) {
            CP_WAIT(1);
        } else {
            CP_WAIT(0);
        }
        __syncthreads();

        uint32_t st = sbase + sidx * STAGE_B;
        const uint32_t aAddr = st + (uint32_t)(wm * 64 + (lane & 15)) * SROWB
                             + (lane >> 4) * 16;
        const uint32_t bAddr = st + 2 * TILE_B
                             + (uint32_t)(wn * 32 + (lane & 7)) * SROWB
                             + ((lane >> 3) & 1) * 16;

        #pragma unroll
        for (int kk = 0; kk < 2; kk++) {
            uint32_t ah[4][4], al[4][4], bb[4][2];
            #pragma unroll
            for (int mt = 0; mt < 4; mt++)
                LDSM4(ah[mt], aAddr + mt * 16 * SROWB + kk * 32);
            #pragma unroll
            for (int nt = 0; nt < 4; nt++)
                LDSM2(bb[nt], bAddr + nt * 8 * SROWB + kk * 32);
            #pragma unroll
            for (int mt = 0; mt < 4; mt++)
                #pragma unroll
                for (int nt = 0; nt < 4; nt++)
                    MMAH(acc[mt][nt], ah[mt], bb[nt]);          // Ahi * B
            #pragma unroll
            for (int mt = 0; mt < 4; mt++)
                LDSM4(al[mt], aAddr + TILE_B + mt * 16 * SROWB + kk * 32);
            #pragma unroll
            for (int mt = 0; mt < 4; mt++)
                #pragma unroll
                for (int nt = 0; nt < 4; nt++)
                    MMAH(acc[mt][nt], al[mt], bb[nt]);          // Alo * B
        }
        __syncthreads();
        if (++sidx == 3) sidx = 0;
    }

    const int rb = blockIdx.y * 128 + wm * 64 + (lane >> 2);
    const int cb = blockIdx.x * 128 + wn * 32 + (lane & 3) * 2;
    #pragma unroll
    for (int mt = 0; mt < 4; mt++)
        #pragma unroll
        for (int nt = 0; nt < 4; nt++) {
            const int row = rb + mt * 16;
            const int col = cb + nt * 8;
            if (OUTH) {
                __half* C = (__half*)Cv;
                *(__half2*)(C + (size_t)row * N + col) =
                    __floats2half2_rn(acc[mt][nt][0], acc[mt][nt][1]);
                *(__half2*)(C + (size_t)(row + 8) * N + col) =
                    __floats2half2_rn(acc[mt][nt][2], acc[mt][nt][3]);
            } else {
                float* C = (float*)Cv;
                *(float2*)(C + (size_t)row * N + col) =
                    make_float2(acc[mt][nt][0], acc[mt][nt][1]);
                *(float2*)(C + (size_t)(row + 8) * N + col) =
                    make_float2(acc[mt][nt][2], acc[mt][nt][3]);
            }
        }
}

// ====================== RoPE + fp16 outputs ======================
__global__ void rope_q(const float* __restrict__ src, const int* __restrict__ pos,
                       __half* __restrict__ qh, __half* __restrict__ ql)
{
    int idx = blockIdx.x * 256 + threadIdx.x;
    if (idx >= TT * NH * 64) return;
    int hh = idx & 63;
    int h  = (idx >> 6) % NH;
    int t  = idx / (64 * NH);

    float e   = (float)hh * (1.0f / 64.0f);
    float inv = 1.0f / powf(10000.0f, e);
    float ang = (float)pos[t] * inv;
    float s, c;
    sincosf(ang, &s, &c);

    size_t base = ((size_t)t * NH + h) * HD + hh;
    float x1 = src[base], x2 = src[base + 64];
    float y1 = (x1 * c - x2 * s) * SCALE;
    float y2 = (x2 * c + x1 * s) * SCALE;
    __half h1 = __float2half_rn(y1), h2 = __float2half_rn(y2);
    qh[base]      = h1;  ql[base]      = __float2half_rn(y1 - __half2float(h1));
    qh[base + 64] = h2;  ql[base + 64] = __float2half_rn(y2 - __half2float(h2));
}

__global__ void rope_k(const float* __restrict__ src, const int* __restrict__ pos,
                       __half* __restrict__ kh)
{
    int idx = blockIdx.x * 256 + threadIdx.x;
    if (idx >= TT * KH * 64) return;
    int hh = idx & 63;
    int h  = (idx >> 6) % KH;
    int t  = idx / (64 * KH);

    float e   = (float)hh * (1.0f / 64.0f);
    float inv = 1.0f / powf(10000.0f, e);
    float ang = (float)pos[t] * inv;
    float s, c;
    sincosf(ang, &s, &c);

    size_t base = ((size_t)t * KH + h) * HD + hh;
    float x1 = src[base], x2 = src[base + 64];
    kh[base]      = __float2half_rn(x1 * c - x2 * s);
    kh[base + 64] = __float2half_rn(x2 * c + x1 * s);
}

// ====================== HMMA flash attention (causal, GQA) ======================
// CTA: 128 q rows x 1 head, 8 warps (16 q rows each). KV tiles of 64.
#define SRH 136
#define SRB 272
#define FL_SMEM ((128 * SRH + 4 * 64 * SRH) * 2)   // Qlo + 2 stages of (K,V)

__global__ __launch_bounds__(256) void flash_h(
    const __half* __restrict__ Qhi, const __half* __restrict__ Qlo,
    const __half* __restrict__ Kv,  const __half* __restrict__ Vv,
    __half* __restrict__ Oh, __half* __restrict__ Ol)
{
    extern __shared__ char fsm[];
    const uint32_t uQlo = smem_to_u32(fsm);
    const uint32_t uSt  = uQlo + 128 * SRB;

    const int tid = threadIdx.x, lane = tid & 31, wid = tid >> 5;
    const int qi = blockIdx.x, n = blockIdx.y, kvh = n >> 2;
    const int tq0 = qi * 128;
    const int ntiles = 2 * qi + 2;

    const __half* Qhg = Qhi + ((size_t)tq0 * NH + n) * HD;
    const __half* Qlg = Qlo + ((size_t)tq0 * NH + n) * HD;
    const __half* Kg  = Kv + (size_t)kvh * HD;
    const __half* Vg  = Vv + (size_t)kvh * HD;

    // ---- stage Qhi (into stage area) + Qlo (persistent) ----
    #pragma unroll
    for (int i = 0; i < 8; i++) {
        int c = tid + 256 * i;
        int row = c >> 4, c16 = c & 15;
        size_t go = (size_t)row * (NH * HD) + c16 * 8;
        CP16(uSt  + (uint32_t)row * SRB + c16 * 16, Qhg + go);
        CP16(uQlo + (uint32_t)row * SRB + c16 * 16, Qlg + go);
    }
    CP_COMMIT();
    CP_WAIT(0);
    __syncthreads();

    uint32_t qh[8][4];
    {
        const uint32_t qa = uSt + (uint32_t)(wid * 16 + (lane & 15)) * SRB
                          + (lane >> 4) * 16;
        #pragma unroll
        for (int dc = 0; dc < 8; dc++)
            LDSM4(qh[dc], qa + dc * 32);
    }
    __syncthreads();   // stage area free for KV

    const uint32_t qlA = uQlo + (uint32_t)(wid * 16 + (lane & 15)) * SRB
                       + (lane >> 4) * 16;
    const int l8 = lane & 7, ls8 = (lane >> 3) & 1;

    float o[16][4];
    #pragma unroll
    for (int i = 0; i < 16; i++)
        #pragma unroll
        for (int j = 0; j < 4; j++) o[i][j] = 0.f;
    float m0 = -1e30f, m1 = -1e30f, l0 = 0.f, l1 = 0.f;

    // preload tile 0
    #pragma unroll
    for (int i = 0; i < 4; i++) {
        int c = tid + 256 * i;
        int row = c >> 4, c16 = c & 15;
        size_t go = (size_t)row * (KH * HD) + c16 * 8;
        CP16(uSt + (uint32_t)row * SRB + c16 * 16, Kg + go);
        CP16(uSt + 64 * SRB + (uint32_t)row * SRB + c16 * 16, Vg + go);
    }
    CP_COMMIT();

    for (int t = 0; t < ntiles; t++) {
        if (t + 1 < ntiles) {
            uint32_t st = uSt + ((t + 1) & 1) * (2 * 64 * SRB);
            const int s0 = (t + 1) * 64;
            #pragma unroll
            for (int i = 0; i < 4; i++) {
                int c = tid + 256 * i;
                int row = c >> 4, c16 = c & 15;
                size_t go = (size_t)(s0 + row) * (KH * HD) + c16 * 8;
                CP16(st + (uint32_t)row * SRB + c16 * 16, Kg + go);
                CP16(st + 64 * SRB + (uint32_t)row * SRB + c16 * 16, Vg + go);
            }
            CP_COMMIT();
            CP_WAIT(1);
        } else {
            CP_WAIT(0);
        }
        __syncthreads();

        const uint32_t uK = uSt + (t & 1) * (2 * 64 * SRB);
        const uint32_t uV = uK + 64 * SRB;

        // ---- S = Q K^T ----  (K smem is [token][dim] == [N,K]: NON-trans B load)
        float s[8][4];
        #pragma unroll
        for (int nt = 0; nt < 8; nt++)
            #pragma unroll
            for (int j = 0; j < 4; j++) s[nt][j] = 0.f;

        #pragma unroll
        for (int dc = 0; dc < 8; dc++) {
            uint32_t ql[4];
            LDSM4(ql, qlA + dc * 32);
            #pragma unroll
            for (int nt = 0; nt < 8; nt++) {
                uint32_t bb[2];
                LDSM2(bb, uK + (uint32_t)(nt * 8 + l8) * SRB + (dc * 16 + ls8 * 8) * 2);
                MMAH(s[nt], qh[dc], bb);
                MMAH(s[nt], ql, bb);
            }
        }

        // ---- causal mask ----
        if (t >= 2 * qi) {
            const int r0 = tq0 + wid * 16 + (lane >> 2);
            const int cB = t * 64 + (lane & 3) * 2;
            #pragma unroll
            for (int nt = 0; nt < 8; nt++) {
                int c0 = cB + nt * 8;
                if (c0     > r0)     s[nt][0] = -1e30f;
                if (c0 + 1 > r0)     s[nt][1] = -1e30f;
                if (c0     > r0 + 8) s[nt][2] = -1e30f;
                if (c0 + 1 > r0 + 8) s[nt][3] = -1e30f;
            }
        }

        // ---- online softmax ----
        float mr0 = -1e30f, mr1 = -1e30f;
        #pragma unroll
        for (int nt = 0; nt < 8; nt++) {
            mr0 = fmaxf(mr0, fmaxf(s[nt][0], s[nt][1]));
            mr1 = fmaxf(mr1, fmaxf(s[nt][2], s[nt][3]));
        }
        mr0 = fmaxf(mr0, __shfl_xor_sync(0xffffffffu, mr0, 1));
        mr0 = fmaxf(mr0, __shfl_xor_sync(0xffffffffu, mr0, 2));
        mr1 = fmaxf(mr1, __shfl_xor_sync(0xffffffffu, mr1, 1));
        mr1 = fmaxf(mr1, __shfl_xor_sync(0xffffffffu, mr1, 2));

        const float mn0 = fmaxf(m0, mr0), mn1 = fmaxf(m1, mr1);
        const float a0 = __expf(m0 - mn0), a1 = __expf(m1 - mn1);
        m0 = mn0; m1 = mn1;

        float ls0 = 0.f, ls1 = 0.f;
        #pragma unroll
        for (int nt = 0; nt < 8; nt++) {
            s[nt][0] = __expf(s[nt][0] - m0); ls0 += s[nt][0];
            s[nt][1] = __expf(s[nt][1] - m0); ls0 += s[nt][1];
            s[nt][2] = __expf(s[nt][2] - m1); ls1 += s[nt][2];
            s[nt][3] = __expf(s[nt][3] - m1); ls1 += s[nt][3];
        }
        ls0 += __shfl_xor_sync(0xffffffffu, ls0, 1);
        ls0 += __shfl_xor_sync(0xffffffffu, ls0, 2);
        ls1 += __shfl_xor_sync(0xffffffffu, ls1, 1);
        ls1 += __shfl_xor_sync(0xffffffffu, ls1, 2);
        l0 = l0 * a0 + ls0;
        l1 = l1 * a1 + ls1;

        #pragma unroll
        for (int i = 0; i < 16; i++) {
            o[i][0] *= a0; o[i][1] *= a0; o[i][2] *= a1; o[i][3] *= a1;
        }

        // ---- P fragments (hi/lo fp16) ----
        uint32_t phi[4][4], plo[4][4];
        #pragma unroll
        for (int kc = 0; kc < 4; kc++) {
            #pragma unroll
            for (int q = 0; q < 4; q++) {
                int nt = 2 * kc + (q >> 1);
                float f0 = s[nt][(q & 1) * 2], f1 = s[nt][(q & 1) * 2 + 1];
                __half2 h = __floats2half2_rn(f0, f1);
                float2 hf = __half22float2(h);
                __half2 l = __floats2half2_rn(f0 - hf.x, f1 - hf.y);
                phi[kc][q] = *(uint32_t*)&h;
                plo[kc][q] = *(uint32_t*)&l;
            }
        }

        // ---- O += P V ----  (V smem is [token=k][dim=n]: trans B load)
        #pragma unroll
        for (int nt2 = 0; nt2 < 16; nt2++) {
            #pragma unroll
            for (int kc = 0; kc < 4; kc++) {
                uint32_t bb[2];
                LDSM2T(bb, uV + (uint32_t)(kc * 16 + ls8 * 8 + l8) * SRB + nt2 * 16);
                MMAH(o[nt2], phi[kc], bb);
                MMAH(o[nt2], plo[kc], bb);
            }
        }
        __syncthreads();
    }

    // ---- epilogue: O / l, write fp16 hi/lo ----
    const float i0 = 1.f / l0, i1 = 1.f / l1;
    const int r0 = tq0 + wid * 16 + (lane >> 2);
    const int cofs = (lane & 3) * 2;
    #pragma unroll
    for (int nt2 = 0; nt2 < 16; nt2++) {
        float v0 = o[nt2][0] * i0, v1 = o[nt2][1] * i0;
        float v2 = o[nt2][2] * i1, v3 = o[nt2][3] * i1;
        size_t p0 = ((size_t)r0 * NH + n) * HD + nt2 * 8 + cofs;
        size_t p1 = ((size_t)(r0 + 8) * NH + n) * HD + nt2 * 8 + cofs;
        __half2 h0 = __floats2half2_rn(v0, v1);
        float2 hf0 = __half22float2(h0);
        __half2 l0h = __floats2half2_rn(v0 - hf0.x, v1 - hf0.y);
        __half2 h1 = __floats2half2_rn(v2, v3);
        float2 hf1 = __half22float2(h1);
        __half2 l1h = __floats2half2_rn(v2 - hf1.x, v3 - hf1.y);
        *(__half2*)(Oh + p0) = h0;  *(__half2*)(Ol + p0) = l0h;
        *(__half2*)(Oh + p1) = h1;  *(__half2*)(Ol + p1) = l1h;
    }
}

// ====================== launch ======================
extern "C" void kernel_launch(void* const* d_in, const int* in_sizes, int n_in,
                              void* d_out, int out_size)
{
    const float* x   = (const float*)d_in[0];
    const int*   pos = (const int*)  d_in[1];
    const float* w_q = (const float*)d_in[2];
    const float* w_k = (const float*)d_in[3];
    const float* w_v = (const float*)d_in[4];
    const float* w_o = (const float*)d_in[5];
    float* out = (float*)d_out;

    float *q, *k;
    cudaGetSymbolAddress((void**)&q, g_q);
    cudaGetSymbolAddress((void**)&k, g_k);
    __half *xh, *xl, *aoh, *aol, *wqT, *wkT, *wvT, *woT, *qh, *ql, *kh, *vh;
    cudaGetSymbolAddress((void**)&xh,  g_xh);  cudaGetSymbolAddress((void**)&xl,  g_xl);
    cudaGetSymbolAddress((void**)&aoh, g_aoh); cudaGetSymbolAddress((void**)&aol, g_aol);
    cudaGetSymbolAddress((void**)&wqT, g_wqT); cudaGetSymbolAddress((void**)&wkT, g_wkT);
    cudaGetSymbolAddress((void**)&wvT, g_wvT); cudaGetSymbolAddress((void**)&woT, g_woT);
    cudaGetSymbolAddress((void**)&qh,  g_qh);  cudaGetSymbolAddress((void**)&ql,  g_ql);
    cudaGetSymbolAddress((void**)&kh,  g_kh);  cudaGetSymbolAddress((void**)&vh,  g_vh);

    cudaFuncSetAttribute(gemm_fh2<0>, cudaFuncAttributeMaxDynamicSharedMemorySize, GEMM_SMEM);
    cudaFuncSetAttribute(gemm_fh2<1>, cudaFuncAttributeMaxDynamicSharedMemorySize, GEMM_SMEM);
    cudaFuncSetAttribute(flash_h,     cudaFuncAttributeMaxDynamicSharedMemorySize, FL_SMEM);

    // operand prep (ordered so the 5th launch is the Q-proj GEMM for ncu -s 5)
    split_f32h<<<(TT*DD/4 + 255)/256, 256>>>(x, xh, xl, TT*DD/4);
    transT_f16<<<dim3(DD/32, DD/32),    256>>>(w_q, wqT, DD, DD);
    transT_f16<<<dim3(KH*HD/32, DD/32), 256>>>(w_k, wkT, DD, KH*HD);
    transT_f16<<<dim3(KH*HD/32, DD/32), 256>>>(w_v, wvT, DD, KH*HD);

    // QKV projections
    gemm_fh2<0><<<dim3(32, 16), 256, GEMM_SMEM>>>(xh, xl, wqT, q,  TT, NH*HD, DD);
    gemm_fh2<0><<<dim3(8, 16),  256, GEMM_SMEM>>>(xh, xl, wkT, k,  TT, KH*HD, DD);
    gemm_fh2<1><<<dim3(8, 16),  256, GEMM_SMEM>>>(xh, xl, wvT, vh, TT, KH*HD, DD);

    transT_f16<<<dim3(DD/32, DD/32),    256>>>(w_o, woT, DD, DD);

    // RoPE -> fp16
    rope_q<<<(TT*NH*64 + 255)/256, 256>>>(q, pos, qh, ql);
    rope_k<<<(TT*KH*64 + 255)/256, 256>>>(k, pos, kh);

    // causal GQA flash attention (HMMA) -> fp16 hi/lo attention output
    flash_h<<<dim3(TT/128, NH), 256, FL_SMEM>>>(qh, ql, kh, vh, aoh, aol);

    // output projection
    gemm_fh2<0><<<dim3(32, 16), 256, GEMM_SMEM>>>(aoh, aol, woT, out, TT, DD, DD);
}

// round 8
// speedup vs baseline: 1.1361x; 1.0524x over previous
#include <cuda_runtime.h>
#include <cuda_fp16.h>
#include <cstdint>
#include <math.h>

// Problem constants
#define TT 2048
#define DD 4096
#define NH 32
#define KH 8
#define HD 128
#define SCALE 0.08838834764831843f   // 1/sqrt(128)

// ====================== PTX helpers (base sm_103-legal only) ======================
__device__ __forceinline__ uint32_t smem_to_u32(const void* p) {
    uint32_t a;
    asm("{ .reg .u64 t; cvta.to.shared.u64 t, %1; cvt.u32.u64 %0, t; }" : "=r"(a) : "l"(p));
    return a;
}
#define CP16(sa, ga) \
    asm volatile("cp.async.cg.shared.global [%0], [%1], 16;" :: "r"(sa), "l"(ga) : "memory")
#define CP_COMMIT() asm volatile("cp.async.commit_group;" ::: "memory")
#define CP_WAIT(n)  asm volatile("cp.async.wait_group %0;" :: "n"(n) : "memory")
#define LDSM4(r, a) \
    asm volatile("ldmatrix.sync.aligned.m8n8.x4.shared.b16 {%0,%1,%2,%3}, [%4];" \
        : "=r"((r)[0]), "=r"((r)[1]), "=r"((r)[2]), "=r"((r)[3]) : "r"(a))
#define LDSM2(r, a) \
    asm volatile("ldmatrix.sync.aligned.m8n8.x2.shared.b16 {%0,%1}, [%2];" \
        : "=r"((r)[0]), "=r"((r)[1]) : "r"(a))
#define LDSM2T(r, a) \
    asm volatile("ldmatrix.sync.aligned.m8n8.x2.trans.shared.b16 {%0,%1}, [%2];" \
        : "=r"((r)[0]), "=r"((r)[1]) : "r"(a))
#define MMAH(d, a, b) \
    asm volatile("mma.sync.aligned.m16n8k16.row.col.f32.f16.f16.f32 " \
        "{%0,%1,%2,%3}, {%4,%5,%6,%7}, {%8,%9}, {%0,%1,%2,%3};" \
        : "+f"((d)[0]), "+f"((d)[1]), "+f"((d)[2]), "+f"((d)[3]) \
        : "r"((a)[0]), "r"((a)[1]), "r"((a)[2]), "r"((a)[3]), "r"((b)[0]), "r"((b)[1]))

// ====================== device scratch ======================
__device__ float  g_q [TT * NH * HD];
__device__ float  g_k [TT * KH * HD];

__device__ __half g_xh [TT * DD],  g_xl [TT * DD];
__device__ __half g_aoh[TT * DD],  g_aol[TT * DD];
__device__ __half g_wqT[DD * DD];                 // transposed [N][K] fp16
__device__ __half g_wkT[KH*HD * DD];
__device__ __half g_wvT[KH*HD * DD];
__device__ __half g_woT[DD * DD];
__device__ __half g_qh [TT * NH * HD], g_ql [TT * NH * HD];
__device__ __half g_kh [TT * KH * HD];
__device__ __half g_vh [TT * KH * HD];

// ====================== fp32 -> fp16 hi/lo split ======================
__global__ void split_f32h(const float* __restrict__ s, __half* __restrict__ hi,
                           __half* __restrict__ lo, int n4)
{
    int i = blockIdx.x * 256 + threadIdx.x;
    if (i >= n4) return;
    float4 f = ((const float4*)s)[i];
    float v[4] = {f.x, f.y, f.z, f.w};
    __align__(8) __half h[4], l[4];
    #pragma unroll
    for (int j = 0; j < 4; j++) {
        h[j] = __float2half_rn(v[j]);
        l[j] = __float2half_rn(v[j] - __half2float(h[j]));
    }
    *(uint2*)(hi + 4 * (size_t)i) = *(uint2*)h;
    *(uint2*)(lo + 4 * (size_t)i) = *(uint2*)l;
}

// transpose fp32 [R,C] -> single fp16 [C,R]
__global__ __launch_bounds__(256) void transT_f16(const float* __restrict__ s,
    __half* __restrict__ d, int R, int C)
{
    __shared__ float t[32][33];
    int bx = blockIdx.x * 32, by = blockIdx.y * 32;
    int tx = threadIdx.x & 31, ty = threadIdx.x >> 5;
    #pragma unroll
    for (int j = 0; j < 4; j++)
        t[ty + 8*j][tx] = s[(size_t)(by + ty + 8*j) * C + bx + tx];
    __syncthreads();
    #pragma unroll
    for (int j = 0; j < 4; j++)
        d[(size_t)(bx + ty + 8*j) * R + by + tx] = __float2half_rn(t[tx][ty + 8*j]);
}

// ====================== mma.sync fp16x2 GEMM core ======================
// 128x128 CTA tile, BK=32, 8 warps (2x4), warp tile 64x32, 3-stage, 1 barrier/stage.
#define SROWB 80                       // smem row stride bytes (32 halves + pad)
#define TILE_B (128 * SROWB)           // 10240
#define STAGE_B (3 * TILE_B)           // Ahi | Alo | B   = 30720
#define GEMM_SMEM (3 * STAGE_B)        // 92160 (3 stages)

struct AccT { float a[4][4][4]; };

__device__ __forceinline__ void gemm_core(
    uint32_t sbase, const __half* pAh, const __half* pAl, const __half* pB,
    int Kd, AccT& A)
{
    const int tid = threadIdx.x, lane = tid & 31, wid = tid >> 5;
    const int wm = wid >> 2, wn = wid & 3;
    const int lrow  = tid >> 2;
    const uint32_t lso = (tid & 3) * 16;
    const int lcolh = (tid & 3) * 8;

    const int nst = Kd >> 5;

    #pragma unroll
    for (int ps = 0; ps < 2; ps++) {         // prologue stages 0,1
        const int k0 = ps << 5;
        uint32_t st = sbase + ps * STAGE_B;
        #pragma unroll
        for (int i = 0; i < 2; i++) {
            int row = lrow + 64 * i;
            uint32_t so = st + (uint32_t)row * SROWB + lso;
            size_t go = (size_t)row * Kd + k0 + lcolh;
            CP16(so,            pAh + go);
            CP16(so + TILE_B,   pAl + go);
            CP16(so + 2*TILE_B, pB  + go);
        }
        CP_COMMIT();
    }

    int sidx = 0;
    for (int s = 0; s < nst; s++) {
        if (s + 1 < nst) { CP_WAIT(1); } else { CP_WAIT(0); }
        __syncthreads();                     // single barrier per stage

        if (s + 2 < nst) {                   // load stage (s+2)%3 (== (s-1)%3, safe now)
            const int k0 = (s + 2) << 5;
            int lidx = sidx - 1; if (lidx < 0) lidx += 3;
            uint32_t st = sbase + lidx * STAGE_B;
            #pragma unroll
            for (int i = 0; i < 2; i++) {
                int row = lrow + 64 * i;
                uint32_t so = st + (uint32_t)row * SROWB + lso;
                size_t go = (size_t)row * Kd + k0 + lcolh;
                CP16(so,            pAh + go);
                CP16(so + TILE_B,   pAl + go);
                CP16(so + 2*TILE_B, pB  + go);
            }
            CP_COMMIT();
        }

        uint32_t st = sbase + sidx * STAGE_B;
        const uint32_t aAddr = st + (uint32_t)(wm * 64 + (lane & 15)) * SROWB
                             + (lane >> 4) * 16;
        const uint32_t bAddr = st + 2 * TILE_B
                             + (uint32_t)(wn * 32 + (lane & 7)) * SROWB
                             + ((lane >> 3) & 1) * 16;

        #pragma unroll
        for (int kk = 0; kk < 2; kk++) {
            uint32_t ah[4][4], al[4][4], bb[4][2];
            #pragma unroll
            for (int mt = 0; mt < 4; mt++)
                LDSM4(ah[mt], aAddr + mt * 16 * SROWB + kk * 32);
            #pragma unroll
            for (int nt = 0; nt < 4; nt++)
                LDSM2(bb[nt], bAddr + nt * 8 * SROWB + kk * 32);
            #pragma unroll
            for (int mt = 0; mt < 4; mt++)
                #pragma unroll
                for (int nt = 0; nt < 4; nt++)
                    MMAH(A.a[mt][nt], ah[mt], bb[nt]);          // Ahi * B
            #pragma unroll
            for (int mt = 0; mt < 4; mt++)
                LDSM4(al[mt], aAddr + TILE_B + mt * 16 * SROWB + kk * 32);
            #pragma unroll
            for (int mt = 0; mt < 4; mt++)
                #pragma unroll
                for (int nt = 0; nt < 4; nt++)
                    MMAH(A.a[mt][nt], al[mt], bb[nt]);          // Alo * B
        }
        if (++sidx == 3) sidx = 0;
    }
}

// ---- merged QKV projection: grid (48, 16) ----
__global__ __launch_bounds__(256) void gemm_qkv(
    const __half* __restrict__ Ahi, const __half* __restrict__ Alo,
    const __half* __restrict__ WQ, const __half* __restrict__ WK,
    const __half* __restrict__ WV,
    float* __restrict__ Cq, float* __restrict__ Ck, __half* __restrict__ Cv)
{
    extern __shared__ char smraw[];
    const uint32_t sbase = smem_to_u32(smraw);
    const int bx = blockIdx.x;
    const int Kd = DD;

    const __half* pB;
    int bn, kind;       // kind 0=q(f32), 1=k(f32), 2=v(f16)
    if (bx < 32)      { pB = WQ; bn = bx;      kind = 0; }
    else if (bx < 40) { pB = WK; bn = bx - 32; kind = 1; }
    else              { pB = WV; bn = bx - 40; kind = 2; }
    pB += (size_t)bn * 128 * Kd;

    AccT A;
    #pragma unroll
    for (int mt = 0; mt < 4; mt++)
        #pragma unroll
        for (int nt = 0; nt < 4; nt++)
            #pragma unroll
            for (int q = 0; q < 4; q++) A.a[mt][nt][q] = 0.f;

    gemm_core(sbase,
              Ahi + (size_t)blockIdx.y * 128 * Kd,
              Alo + (size_t)blockIdx.y * 128 * Kd, pB, Kd, A);

    const int lane = threadIdx.x & 31, wid = threadIdx.x >> 5;
    const int wm = wid >> 2, wn = wid & 3;
    const int rb = blockIdx.y * 128 + wm * 64 + (lane >> 2);
    const int cbl = bn * 128 + wn * 32 + (lane & 3) * 2;
    const int Nloc = (kind == 0) ? NH * HD : KH * HD;

    #pragma unroll
    for (int mt = 0; mt < 4; mt++)
        #pragma unroll
        for (int nt = 0; nt < 4; nt++) {
            const int row = rb + mt * 16;
            const int col = cbl + nt * 8;
            if (kind == 2) {
                *(__half2*)(Cv + (size_t)row * Nloc + col) =
                    __floats2half2_rn(A.a[mt][nt][0], A.a[mt][nt][1]);
                *(__half2*)(Cv + (size_t)(row + 8) * Nloc + col) =
                    __floats2half2_rn(A.a[mt][nt][2], A.a[mt][nt][3]);
            } else {
                float* C = (kind == 0) ? Cq : Ck;
                *(float2*)(C + (size_t)row * Nloc + col) =
                    make_float2(A.a[mt][nt][0], A.a[mt][nt][1]);
                *(float2*)(C + (size_t)(row + 8) * Nloc + col) =
                    make_float2(A.a[mt][nt][2], A.a[mt][nt][3]);
            }
        }
}

// ---- o-proj: C fp32, grid (32, 16) ----
__global__ __launch_bounds__(256) void gemm_o(
    const __half* __restrict__ Ahi, const __half* __restrict__ Alo,
    const __half* __restrict__ BT, float* __restrict__ C)
{
    extern __shared__ char smraw[];
    const uint32_t sbase = smem_to_u32(smraw);
    const int Kd = DD, N = DD;

    AccT A;
    #pragma unroll
    for (int mt = 0; mt < 4; mt++)
        #pragma unroll
        for (int nt = 0; nt < 4; nt++)
            #pragma unroll
            for (int q = 0; q < 4; q++) A.a[mt][nt][q] = 0.f;

    gemm_core(sbase,
              Ahi + (size_t)blockIdx.y * 128 * Kd,
              Alo + (size_t)blockIdx.y * 128 * Kd,
              BT + (size_t)blockIdx.x * 128 * Kd, Kd, A);

    const int lane = threadIdx.x & 31, wid = threadIdx.x >> 5;
    const int wm = wid >> 2, wn = wid & 3;
    const int rb = blockIdx.y * 128 + wm * 64 + (lane >> 2);
    const int cb = blockIdx.x * 128 + wn * 32 + (lane & 3) * 2;
    #pragma unroll
    for (int mt = 0; mt < 4; mt++)
        #pragma unroll
        for (int nt = 0; nt < 4; nt++) {
            const int row = rb + mt * 16;
            const int col = cb + nt * 8;
            *(float2*)(C + (size_t)row * N + col) =
                make_float2(A.a[mt][nt][0], A.a[mt][nt][1]);
            *(float2*)(C + (size_t)(row + 8) * N + col) =
                make_float2(A.a[mt][nt][2], A.a[mt][nt][3]);
        }
}

// ====================== RoPE + fp16 outputs ======================
__global__ void rope_q(const float* __restrict__ src, const int* __restrict__ pos,
                       __half* __restrict__ qh, __half* __restrict__ ql)
{
    int idx = blockIdx.x * 256 + threadIdx.x;
    if (idx >= TT * NH * 64) return;
    int hh = idx & 63;
    int h  = (idx >> 6) % NH;
    int t  = idx / (64 * NH);

    float e   = (float)hh * (1.0f / 64.0f);
    float inv = 1.0f / powf(10000.0f, e);
    float ang = (float)pos[t] * inv;
    float s, c;
    sincosf(ang, &s, &c);

    size_t base = ((size_t)t * NH + h) * HD + hh;
    float x1 = src[base], x2 = src[base + 64];
    float y1 = (x1 * c - x2 * s) * SCALE;
    float y2 = (x2 * c + x1 * s) * SCALE;
    __half h1 = __float2half_rn(y1), h2 = __float2half_rn(y2);
    qh[base]      = h1;  ql[base]      = __float2half_rn(y1 - __half2float(h1));
    qh[base + 64] = h2;  ql[base + 64] = __float2half_rn(y2 - __half2float(h2));
}

__global__ void rope_k(const float* __restrict__ src, const int* __restrict__ pos,
                       __half* __restrict__ kh)
{
    int idx = blockIdx.x * 256 + threadIdx.x;
    if (idx >= TT * KH * 64) return;
    int hh = idx & 63;
    int h  = (idx >> 6) % KH;
    int t  = idx / (64 * KH);

    float e   = (float)hh * (1.0f / 64.0f);
    float inv = 1.0f / powf(10000.0f, e);
    float ang = (float)pos[t] * inv;
    float s, c;
    sincosf(ang, &s, &c);

    size_t base = ((size_t)t * KH + h) * HD + hh;
    float x1 = src[base], x2 = src[base + 64];
    kh[base]      = __float2half_rn(x1 * c - x2 * s);
    kh[base + 64] = __float2half_rn(x2 * c + x1 * s);
}

// ====================== HMMA flash attention (causal, GQA) ======================
// CTA: 128 q rows x 1 head, 8 warps (16 q rows each). KV tiles of 64.
#define SRH 136
#define SRB 272
#define FL_SMEM ((128 * SRH + 4 * 64 * SRH) * 2)   // Qlo + 2 stages of (K,V)

__global__ __launch_bounds__(256) void flash_h(
    const __half* __restrict__ Qhi, const __half* __restrict__ Qlo,
    const __half* __restrict__ Kv,  const __half* __restrict__ Vv,
    __half* __restrict__ Oh, __half* __restrict__ Ol)
{
    extern __shared__ char fsm[];
    const uint32_t uQlo = smem_to_u32(fsm);
    const uint32_t uSt  = uQlo + 128 * SRB;

    const int tid = threadIdx.x, lane = tid & 31, wid = tid >> 5;
    const int qi = gridDim.x - 1 - blockIdx.x;     // heavy tiles first
    const int n = blockIdx.y, kvh = n >> 2;
    const int tq0 = qi * 128;
    const int ntiles = 2 * qi + 2;

    const __half* Qhg = Qhi + ((size_t)tq0 * NH + n) * HD;
    const __half* Qlg = Qlo + ((size_t)tq0 * NH + n) * HD;
    const __half* Kg  = Kv + (size_t)kvh * HD;
    const __half* Vg  = Vv + (size_t)kvh * HD;

    // ---- stage Qhi (into stage area) + Qlo (persistent) ----
    #pragma unroll
    for (int i = 0; i < 8; i++) {
        int c = tid + 256 * i;
        int row = c >> 4, c16 = c & 15;
        size_t go = (size_t)row * (NH * HD) + c16 * 8;
        CP16(uSt  + (uint32_t)row * SRB + c16 * 16, Qhg + go);
        CP16(uQlo + (uint32_t)row * SRB + c16 * 16, Qlg + go);
    }
    CP_COMMIT();
    CP_WAIT(0);
    __syncthreads();

    uint32_t qh[8][4];
    {
        const uint32_t qa = uSt + (uint32_t)(wid * 16 + (lane & 15)) * SRB
                          + (lane >> 4) * 16;
        #pragma unroll
        for (int dc = 0; dc < 8; dc++)
            LDSM4(qh[dc], qa + dc * 32);
    }
    __syncthreads();   // stage area free for KV

    const uint32_t qlA = uQlo + (uint32_t)(wid * 16 + (lane & 15)) * SRB
                       + (lane >> 4) * 16;
    const int l8 = lane & 7, ls8 = (lane >> 3) & 1;

    float o[16][4];
    #pragma unroll
    for (int i = 0; i < 16; i++)
        #pragma unroll
        for (int j = 0; j < 4; j++) o[i][j] = 0.f;
    float m0 = -1e30f, m1 = -1e30f, l0 = 0.f, l1 = 0.f;

    // preload tile 0
    #pragma unroll
    for (int i = 0; i < 4; i++) {
        int c = tid + 256 * i;
        int row = c >> 4, c16 = c & 15;
        size_t go = (size_t)row * (KH * HD) + c16 * 8;
        CP16(uSt + (uint32_t)row * SRB + c16 * 16, Kg + go);
        CP16(uSt + 64 * SRB + (uint32_t)row * SRB + c16 * 16, Vg + go);
    }
    CP_COMMIT();

    for (int t = 0; t < ntiles; t++) {
        CP_WAIT(0);
        __syncthreads();                 // tile t visible; all done reading stage (t+1)&1

        if (t + 1 < ntiles) {
            uint32_t st = uSt + ((t + 1) & 1) * (2 * 64 * SRB);
            const int s0 = (t + 1) * 64;
            #pragma unroll
            for (int i = 0; i < 4; i++) {
                int c = tid + 256 * i;
                int row = c >> 4, c16 = c & 15;
                size_t go = (size_t)(s0 + row) * (KH * HD) + c16 * 8;
                CP16(st + (uint32_t)row * SRB + c16 * 16, Kg + go);
                CP16(st + 64 * SRB + (uint32_t)row * SRB + c16 * 16, Vg + go);
            }
            CP_COMMIT();
        }

        const uint32_t uK = uSt + (t & 1) * (2 * 64 * SRB);
        const uint32_t uV = uK + 64 * SRB;

        // ---- S = Q K^T ----  (K smem is [token][dim] == [N,K]: NON-trans B load)
        float s[8][4];
        #pragma unroll
        for (int nt = 0; nt < 8; nt++)
            #pragma unroll
            for (int j = 0; j < 4; j++) s[nt][j] = 0.f;

        #pragma unroll
        for (int dc = 0; dc < 8; dc++) {
            uint32_t ql[4];
            LDSM4(ql, qlA + dc * 32);
            #pragma unroll
            for (int nt = 0; nt < 8; nt++) {
                uint32_t bb[2];
                LDSM2(bb, uK + (uint32_t)(nt * 8 + l8) * SRB + (dc * 16 + ls8 * 8) * 2);
                MMAH(s[nt], qh[dc], bb);
                MMAH(s[nt], ql, bb);
            }
        }

        // ---- causal mask ----
        if (t >= 2 * qi) {
            const int r0 = tq0 + wid * 16 + (lane >> 2);
            const int cB = t * 64 + (lane & 3) * 2;
            #pragma unroll
            for (int nt = 0; nt < 8; nt++) {
                int c0 = cB + nt * 8;
                if (c0     > r0)     s[nt][0] = -1e30f;
                if (c0 + 1 > r0)     s[nt][1] = -1e30f;
                if (c0     > r0 + 8) s[nt][2] = -1e30f;
                if (c0 + 1 > r0 + 8) s[nt][3] = -1e30f;
            }
        }

        // ---- online softmax ----
        float mr0 = -1e30f, mr1 = -1e30f;
        #pragma unroll
        for (int nt = 0; nt < 8; nt++) {
            mr0 = fmaxf(mr0, fmaxf(s[nt][0], s[nt][1]));
            mr1 = fmaxf(mr1, fmaxf(s[nt][2], s[nt][3]));
        }
        mr0 = fmaxf(mr0, __shfl_xor_sync(0xffffffffu, mr0, 1));
        mr0 = fmaxf(mr0, __shfl_xor_sync(0xffffffffu, mr0, 2));
        mr1 = fmaxf(mr1, __shfl_xor_sync(0xffffffffu, mr1, 1));
        mr1 = fmaxf(mr1, __shfl_xor_sync(0xffffffffu, mr1, 2));

        const float mn0 = fmaxf(m0, mr0), mn1 = fmaxf(m1, mr1);
        const float a0 = __expf(m0 - mn0), a1 = __expf(m1 - mn1);
        m0 = mn0; m1 = mn1;

        float ls0 = 0.f, ls1 = 0.f;
        #pragma unroll
        for (int nt = 0; nt < 8; nt++) {
            s[nt][0] = __expf(s[nt][0] - m0); ls0 += s[nt][0];
            s[nt][1] = __expf(s[nt][1] - m0); ls0 += s[nt][1];
            s[nt][2] = __expf(s[nt][2] - m1); ls1 += s[nt][2];
            s[nt][3] = __expf(s[nt][3] - m1); ls1 += s[nt][3];
        }
        ls0 += __shfl_xor_sync(0xffffffffu, ls0, 1);
        ls0 += __shfl_xor_sync(0xffffffffu, ls0, 2);
        ls1 += __shfl_xor_sync(0xffffffffu, ls1, 1);
        ls1 += __shfl_xor_sync(0xffffffffu, ls1, 2);
        l0 = l0 * a0 + ls0;
        l1 = l1 * a1 + ls1;

        #pragma unroll
        for (int i = 0; i < 16; i++) {
            o[i][0] *= a0; o[i][1] *= a0; o[i][2] *= a1; o[i][3] *= a1;
        }

        // ---- P fragments (hi/lo fp16) ----
        uint32_t phi[4][4], plo[4][4];
        #pragma unroll
        for (int kc = 0; kc < 4; kc++) {
            #pragma unroll
            for (int q = 0; q < 4; q++) {
                int nt = 2 * kc + (q >> 1);
                float f0 = s[nt][(q & 1) * 2], f1 = s[nt][(q & 1) * 2 + 1];
                __half2 h = __floats2half2_rn(f0, f1);
                float2 hf = __half22float2(h);
                __half2 l = __floats2half2_rn(f0 - hf.x, f1 - hf.y);
                phi[kc][q] = *(uint32_t*)&h;
                plo[kc][q] = *(uint32_t*)&l;
            }
        }

        // ---- O += P V ----  (V smem is [token=k][dim=n]: trans B load)
        #pragma unroll
        for (int nt2 = 0; nt2 < 16; nt2++) {
            #pragma unroll
            for (int kc = 0; kc < 4; kc++) {
                uint32_t bb[2];
                LDSM2T(bb, uV + (uint32_t)(kc * 16 + ls8 * 8 + l8) * SRB + nt2 * 16);
                MMAH(o[nt2], phi[kc], bb);
                MMAH(o[nt2], plo[kc], bb);
            }
        }
    }

    // ---- epilogue: O / l, write fp16 hi/lo ----
    const float i0 = 1.f / l0, i1 = 1.f / l1;
    const int r0 = tq0 + wid * 16 + (lane >> 2);
    const int cofs = (lane & 3) * 2;
    #pragma unroll
    for (int nt2 = 0; nt2 < 16; nt2++) {
        float v0 = o[nt2][0] * i0, v1 = o[nt2][1] * i0;
        float v2 = o[nt2][2] * i1, v3 = o[nt2][3] * i1;
        size_t p0 = ((size_t)r0 * NH + n) * HD + nt2 * 8 + cofs;
        size_t p1 = ((size_t)(r0 + 8) * NH + n) * HD + nt2 * 8 + cofs;
        __half2 h0 = __floats2half2_rn(v0, v1);
        float2 hf0 = __half22float2(h0);
        __half2 l0h = __floats2half2_rn(v0 - hf0.x, v1 - hf0.y);
        __half2 h1 = __floats2half2_rn(v2, v3);
        float2 hf1 = __half22float2(h1);
        __half2 l1h = __floats2half2_rn(v2 - hf1.x, v3 - hf1.y);
        *(__half2*)(Oh + p0) = h0;  *(__half2*)(Ol + p0) = l0h;
        *(__half2*)(Oh + p1) = h1;  *(__half2*)(Ol + p1) = l1h;
    }
}

// ====================== launch ======================
extern "C" void kernel_launch(void* const* d_in, const int* in_sizes, int n_in,
                              void* d_out, int out_size)
{
    const float* x   = (const float*)d_in[0];
    const int*   pos = (const int*)  d_in[1];
    const float* w_q = (const float*)d_in[2];
    const float* w_k = (const float*)d_in[3];
    const float* w_v = (const float*)d_in[4];
    const float* w_o = (const float*)d_in[5];
    float* out = (float*)d_out;

    float *q, *k;
    cudaGetSymbolAddress((void**)&q, g_q);
    cudaGetSymbolAddress((void**)&k, g_k);
    __half *xh, *xl, *aoh, *aol, *wqT, *wkT, *wvT, *woT, *qh, *ql, *kh, *vh;
    cudaGetSymbolAddress((void**)&xh,  g_xh);  cudaGetSymbolAddress((void**)&xl,  g_xl);
    cudaGetSymbolAddress((void**)&aoh, g_aoh); cudaGetSymbolAddress((void**)&aol, g_aol);
    cudaGetSymbolAddress((void**)&wqT, g_wqT); cudaGetSymbolAddress((void**)&wkT, g_wkT);
    cudaGetSymbolAddress((void**)&wvT, g_wvT); cudaGetSymbolAddress((void**)&woT, g_woT);
    cudaGetSymbolAddress((void**)&qh,  g_qh);  cudaGetSymbolAddress((void**)&ql,  g_ql);
    cudaGetSymbolAddress((void**)&kh,  g_kh);  cudaGetSymbolAddress((void**)&vh,  g_vh);

    cudaFuncSetAttribute(gemm_qkv, cudaFuncAttributeMaxDynamicSharedMemorySize, GEMM_SMEM);
    cudaFuncSetAttribute(gemm_o,   cudaFuncAttributeMaxDynamicSharedMemorySize, GEMM_SMEM);
    cudaFuncSetAttribute(flash_h,  cudaFuncAttributeMaxDynamicSharedMemorySize, FL_SMEM);

    // operand prep (ordered so the 5th launch is the merged QKV GEMM for ncu -s 5)
    split_f32h<<<(TT*DD/4 + 255)/256, 256>>>(x, xh, xl, TT*DD/4);
    transT_f16<<<dim3(DD/32, DD/32),    256>>>(w_q, wqT, DD, DD);
    transT_f16<<<dim3(KH*HD/32, DD/32), 256>>>(w_k, wkT, DD, KH*HD);
    transT_f16<<<dim3(KH*HD/32, DD/32), 256>>>(w_v, wvT, DD, KH*HD);

    // merged QKV projection
    gemm_qkv<<<dim3(48, 16), 256, GEMM_SMEM>>>(xh, xl, wqT, wkT, wvT, q, k, vh);

    transT_f16<<<dim3(DD/32, DD/32),    256>>>(w_o, woT, DD, DD);

    // RoPE -> fp16
    rope_q<<<(TT*NH*64 + 255)/256, 256>>>(q, pos, qh, ql);
    rope_k<<<(TT*KH*64 + 255)/256, 256>>>(k, pos, kh);

    // causal GQA flash attention (HMMA) -> fp16 hi/lo attention output
    flash_h<<<dim3(TT/128, NH), 256, FL_SMEM>>>(qh, ql, kh, vh, aoh, aol);

    // output projection
    gemm_o<<<dim3(32, 16), 256, GEMM_SMEM>>>(aoh, aol, woT, out);
}

// round 9
// speedup vs baseline: 1.2974x; 1.1420x over previous
#include <cuda_runtime.h>
#include <cuda_fp16.h>
#include <cstdint>
#include <math.h>

// Problem constants
#define TT 2048
#define DD 4096
#define NH 32
#define KH 8
#define HD 128
#define SCALE 0.08838834764831843f   // 1/sqrt(128)

// ====================== PTX helpers (base sm_103-legal only) ======================
__device__ __forceinline__ uint32_t smem_to_u32(const void* p) {
    uint32_t a;
    asm("{ .reg .u64 t; cvta.to.shared.u64 t, %1; cvt.u32.u64 %0, t; }" : "=r"(a) : "l"(p));
    return a;
}
#define CP16(sa, ga) \
    asm volatile("cp.async.cg.shared.global [%0], [%1], 16;" :: "r"(sa), "l"(ga) : "memory")
#define CP_COMMIT() asm volatile("cp.async.commit_group;" ::: "memory")
#define CP_WAIT(n)  asm volatile("cp.async.wait_group %0;" :: "n"(n) : "memory")
#define LDSM4(r, a) \
    asm volatile("ldmatrix.sync.aligned.m8n8.x4.shared.b16 {%0,%1,%2,%3}, [%4];" \
        : "=r"((r)[0]), "=r"((r)[1]), "=r"((r)[2]), "=r"((r)[3]) : "r"(a))
#define LDSM4T(r, a) \
    asm volatile("ldmatrix.sync.aligned.m8n8.x4.trans.shared.b16 {%0,%1,%2,%3}, [%4];" \
        : "=r"((r)[0]), "=r"((r)[1]), "=r"((r)[2]), "=r"((r)[3]) : "r"(a))
#define LDSM2(r, a) \
    asm volatile("ldmatrix.sync.aligned.m8n8.x2.shared.b16 {%0,%1}, [%2];" \
        : "=r"((r)[0]), "=r"((r)[1]) : "r"(a))
#define MMAH(d, a, b) \
    asm volatile("mma.sync.aligned.m16n8k16.row.col.f32.f16.f16.f32 " \
        "{%0,%1,%2,%3}, {%4,%5,%6,%7}, {%8,%9}, {%0,%1,%2,%3};" \
        : "+f"((d)[0]), "+f"((d)[1]), "+f"((d)[2]), "+f"((d)[3]) \
        : "r"((a)[0]), "r"((a)[1]), "r"((a)[2]), "r"((a)[3]), "r"((b)[0]), "r"((b)[1]))

// ====================== device scratch ======================
__device__ float  g_q [TT * NH * HD];
__device__ float  g_k [TT * KH * HD];

__device__ __half g_xh [TT * DD],  g_xl [TT * DD];
__device__ __half g_aoh[TT * DD];
__device__ __half g_wqT[DD * DD];                 // transposed [N][K] fp16
__device__ __half g_wkT[KH*HD * DD];
__device__ __half g_wvT[KH*HD * DD];
__device__ __half g_woT[DD * DD];
__device__ __half g_qh [TT * NH * HD], g_ql [TT * NH * HD];
__device__ __half g_kh [TT * KH * HD];
__device__ __half g_vh [TT * KH * HD];

// ====================== fp32 -> fp16 hi/lo split ======================
__global__ void split_f32h(const float* __restrict__ s, __half* __restrict__ hi,
                           __half* __restrict__ lo, int n4)
{
    int i = blockIdx.x * 256 + threadIdx.x;
    if (i >= n4) return;
    float4 f = ((const float4*)s)[i];
    float v[4] = {f.x, f.y, f.z, f.w};
    __align__(8) __half h[4], l[4];
    #pragma unroll
    for (int j = 0; j < 4; j++) {
        h[j] = __float2half_rn(v[j]);
        l[j] = __float2half_rn(v[j] - __half2float(h[j]));
    }
    *(uint2*)(hi + 4 * (size_t)i) = *(uint2*)h;
    *(uint2*)(lo + 4 * (size_t)i) = *(uint2*)l;
}

// transpose fp32 [R,C] -> single fp16 [C,R]
__global__ __launch_bounds__(256) void transT_f16(const float* __restrict__ s,
    __half* __restrict__ d, int R, int C)
{
    __shared__ float t[32][33];
    int bx = blockIdx.x * 32, by = blockIdx.y * 32;
    int tx = threadIdx.x & 31, ty = threadIdx.x >> 5;
    #pragma unroll
    for (int j = 0; j < 4; j++)
        t[ty + 8*j][tx] = s[(size_t)(by + ty + 8*j) * C + bx + tx];
    __syncthreads();
    #pragma unroll
    for (int j = 0; j < 4; j++)
        d[(size_t)(bx + ty + 8*j) * R + by + tx] = __float2half_rn(t[tx][ty + 8*j]);
}

// ====================== mma.sync GEMM core ======================
// 128x128 CTA tile, BK=32, 8 warps (2x4), warp tile 64x32, 3-stage, 1 barrier/stage.
// NT=2: A = Ahi+Alo (two MMA terms).  NT=1: A = Ahi only.
#define SROWB 80                       // smem row stride bytes (32 halves + pad)
#define TILE_B (128 * SROWB)           // 10240
#define STAGE_B (3 * TILE_B)           // Ahi | Alo | B   = 30720
#define GEMM_SMEM (3 * STAGE_B)        // 92160 (3 stages)

struct AccT { float a[4][4][4]; };

template <int NT>
__device__ __forceinline__ void gemm_core(
    uint32_t sbase, const __half* pAh, const __half* pAl, const __half* pB,
    int Kd, AccT& A)
{
    const int tid = threadIdx.x, lane = tid & 31, wid = tid >> 5;
    const int wm = wid >> 2, wn = wid & 3;
    const int lrow  = tid >> 2;
    const uint32_t lso = (tid & 3) * 16;
    const int lcolh = (tid & 3) * 8;

    const int nst = Kd >> 5;

    #pragma unroll
    for (int ps = 0; ps < 2; ps++) {         // prologue stages 0,1
        const int k0 = ps << 5;
        uint32_t st = sbase + ps * STAGE_B;
        #pragma unroll
        for (int i = 0; i < 2; i++) {
            int row = lrow + 64 * i;
            uint32_t so = st + (uint32_t)row * SROWB + lso;
            size_t go = (size_t)row * Kd + k0 + lcolh;
            CP16(so,            pAh + go);
            if (NT == 2) CP16(so + TILE_B, pAl + go);
            CP16(so + 2*TILE_B, pB  + go);
        }
        CP_COMMIT();
    }

    int sidx = 0;
    for (int s = 0; s < nst; s++) {
        if (s + 1 < nst) { CP_WAIT(1); } else { CP_WAIT(0); }
        __syncthreads();                     // single barrier per stage

        if (s + 2 < nst) {
            const int k0 = (s + 2) << 5;
            int lidx = sidx - 1; if (lidx < 0) lidx += 3;
            uint32_t st = sbase + lidx * STAGE_B;
            #pragma unroll
            for (int i = 0; i < 2; i++) {
                int row = lrow + 64 * i;
                uint32_t so = st + (uint32_t)row * SROWB + lso;
                size_t go = (size_t)row * Kd + k0 + lcolh;
                CP16(so,            pAh + go);
                if (NT == 2) CP16(so + TILE_B, pAl + go);
                CP16(so + 2*TILE_B, pB  + go);
            }
            CP_COMMIT();
        }

        uint32_t st = sbase + sidx * STAGE_B;
        const uint32_t aAddr = st + (uint32_t)(wm * 64 + (lane & 15)) * SROWB
                             + (lane >> 4) * 16;
        const uint32_t bAddr = st + 2 * TILE_B
                             + (uint32_t)(wn * 32 + (lane & 7)) * SROWB
                             + ((lane >> 3) & 1) * 16;

        #pragma unroll
        for (int kk = 0; kk < 2; kk++) {
            uint32_t ah[4][4], bb[4][2];
            #pragma unroll
            for (int mt = 0; mt < 4; mt++)
                LDSM4(ah[mt], aAddr + mt * 16 * SROWB + kk * 32);
            #pragma unroll
            for (int nt = 0; nt < 4; nt++)
                LDSM2(bb[nt], bAddr + nt * 8 * SROWB + kk * 32);
            #pragma unroll
            for (int mt = 0; mt < 4; mt++)
                #pragma unroll
                for (int nt = 0; nt < 4; nt++)
                    MMAH(A.a[mt][nt], ah[mt], bb[nt]);          // Ahi * B
            if (NT == 2) {
                uint32_t al[4][4];
                #pragma unroll
                for (int mt = 0; mt < 4; mt++)
                    LDSM4(al[mt], aAddr + TILE_B + mt * 16 * SROWB + kk * 32);
                #pragma unroll
                for (int mt = 0; mt < 4; mt++)
                    #pragma unroll
                    for (int nt = 0; nt < 4; nt++)
                        MMAH(A.a[mt][nt], al[mt], bb[nt]);      // Alo * B
            }
        }
        if (++sidx == 3) sidx = 0;
    }
}

// ---- merged QKV projection: grid (48, 16) ----
__global__ __launch_bounds__(256) void gemm_qkv(
    const __half* __restrict__ Ahi, const __half* __restrict__ Alo,
    const __half* __restrict__ WQ, const __half* __restrict__ WK,
    const __half* __restrict__ WV,
    float* __restrict__ Cq, float* __restrict__ Ck, __half* __restrict__ Cv)
{
    extern __shared__ char smraw[];
    const uint32_t sbase = smem_to_u32(smraw);
    const int bx = blockIdx.x;
    const int Kd = DD;

    const __half* pB;
    int bn, kind;       // kind 0=q(f32), 1=k(f32), 2=v(f16)
    if (bx < 32)      { pB = WQ; bn = bx;      kind = 0; }
    else if (bx < 40) { pB = WK; bn = bx - 32; kind = 1; }
    else              { pB = WV; bn = bx - 40; kind = 2; }
    pB += (size_t)bn * 128 * Kd;

    AccT A;
    #pragma unroll
    for (int mt = 0; mt < 4; mt++)
        #pragma unroll
        for (int nt = 0; nt < 4; nt++)
            #pragma unroll
            for (int q = 0; q < 4; q++) A.a[mt][nt][q] = 0.f;

    gemm_core<2>(sbase,
                 Ahi + (size_t)blockIdx.y * 128 * Kd,
                 Alo + (size_t)blockIdx.y * 128 * Kd, pB, Kd, A);

    const int lane = threadIdx.x & 31, wid = threadIdx.x >> 5;
    const int wm = wid >> 2, wn = wid & 3;
    const int rb = blockIdx.y * 128 + wm * 64 + (lane >> 2);
    const int cbl = bn * 128 + wn * 32 + (lane & 3) * 2;
    const int Nloc = (kind == 0) ? NH * HD : KH * HD;

    #pragma unroll
    for (int mt = 0; mt < 4; mt++)
        #pragma unroll
        for (int nt = 0; nt < 4; nt++) {
            const int row = rb + mt * 16;
            const int col = cbl + nt * 8;
            if (kind == 2) {
                *(__half2*)(Cv + (size_t)row * Nloc + col) =
                    __floats2half2_rn(A.a[mt][nt][0], A.a[mt][nt][1]);
                *(__half2*)(Cv + (size_t)(row + 8) * Nloc + col) =
                    __floats2half2_rn(A.a[mt][nt][2], A.a[mt][nt][3]);
            } else {
                float* C = (kind == 0) ? Cq : Ck;
                *(float2*)(C + (size_t)row * Nloc + col) =
                    make_float2(A.a[mt][nt][0], A.a[mt][nt][1]);
                *(float2*)(C + (size_t)(row + 8) * Nloc + col) =
                    make_float2(A.a[mt][nt][2], A.a[mt][nt][3]);
            }
        }
}

// ---- o-proj: single-term A (ao fp16), C fp32, grid (32, 16) ----
__global__ __launch_bounds__(256) void gemm_o(
    const __half* __restrict__ Ah, const __half* __restrict__ BT,
    float* __restrict__ C)
{
    extern __shared__ char smraw[];
    const uint32_t sbase = smem_to_u32(smraw);
    const int Kd = DD, N = DD;

    AccT A;
    #pragma unroll
    for (int mt = 0; mt < 4; mt++)
        #pragma unroll
        for (int nt = 0; nt < 4; nt++)
            #pragma unroll
            for (int q = 0; q < 4; q++) A.a[mt][nt][q] = 0.f;

    gemm_core<1>(sbase,
                 Ah + (size_t)blockIdx.y * 128 * Kd, (const __half*)0,
                 BT + (size_t)blockIdx.x * 128 * Kd, Kd, A);

    const int lane = threadIdx.x & 31, wid = threadIdx.x >> 5;
    const int wm = wid >> 2, wn = wid & 3;
    const int rb = blockIdx.y * 128 + wm * 64 + (lane >> 2);
    const int cb = blockIdx.x * 128 + wn * 32 + (lane & 3) * 2;
    #pragma unroll
    for (int mt = 0; mt < 4; mt++)
        #pragma unroll
        for (int nt = 0; nt < 4; nt++) {
            const int row = rb + mt * 16;
            const int col = cb + nt * 8;
            *(float2*)(C + (size_t)row * N + col) =
                make_float2(A.a[mt][nt][0], A.a[mt][nt][1]);
            *(float2*)(C + (size_t)(row + 8) * N + col) =
                make_float2(A.a[mt][nt][2], A.a[mt][nt][3]);
        }
}

// ====================== RoPE + fp16 outputs ======================
__global__ void rope_q(const float* __restrict__ src, const int* __restrict__ pos,
                       __half* __restrict__ qh, __half* __restrict__ ql)
{
    int idx = blockIdx.x * 256 + threadIdx.x;
    if (idx >= TT * NH * 64) return;
    int hh = idx & 63;
    int h  = (idx >> 6) % NH;
    int t  = idx / (64 * NH);

    float e   = (float)hh * (1.0f / 64.0f);
    float inv = 1.0f / powf(10000.0f, e);
    float ang = (float)pos[t] * inv;
    float s, c;
    sincosf(ang, &s, &c);

    size_t base = ((size_t)t * NH + h) * HD + hh;
    float x1 = src[base], x2 = src[base + 64];
    float y1 = (x1 * c - x2 * s) * SCALE;
    float y2 = (x2 * c + x1 * s) * SCALE;
    __half h1 = __float2half_rn(y1), h2 = __float2half_rn(y2);
    qh[base]      = h1;  ql[base]      = __float2half_rn(y1 - __half2float(h1));
    qh[base + 64] = h2;  ql[base + 64] = __float2half_rn(y2 - __half2float(h2));
}

__global__ void rope_k(const float* __restrict__ src, const int* __restrict__ pos,
                       __half* __restrict__ kh)
{
    int idx = blockIdx.x * 256 + threadIdx.x;
    if (idx >= TT * KH * 64) return;
    int hh = idx & 63;
    int h  = (idx >> 6) % KH;
    int t  = idx / (64 * KH);

    float e   = (float)hh * (1.0f / 64.0f);
    float inv = 1.0f / powf(10000.0f, e);
    float ang = (float)pos[t] * inv;
    float s, c;
    sincosf(ang, &s, &c);

    size_t base = ((size_t)t * KH + h) * HD + hh;
    float x1 = src[base], x2 = src[base + 64];
    kh[base]      = __float2half_rn(x1 * c - x2 * s);
    kh[base + 64] = __float2half_rn(x2 * c + x1 * s);
}

// ====================== HMMA flash attention (causal, GQA) ======================
// CTA: 128 q rows x 1 head, 8 warps (16 q rows each). KV tiles of 64.
#define SRH 136
#define SRB 272
#define FL_SMEM ((128 * SRH + 4 * 64 * SRH) * 2)   // Qlo + 2 stages of (K,V)

__global__ __launch_bounds__(256) void flash_h(
    const __half* __restrict__ Qhi, const __half* __restrict__ Qlo,
    const __half* __restrict__ Kv,  const __half* __restrict__ Vv,
    __half* __restrict__ Oh)
{
    extern __shared__ char fsm[];
    const uint32_t uQlo = smem_to_u32(fsm);
    const uint32_t uSt  = uQlo + 128 * SRB;

    const int tid = threadIdx.x, lane = tid & 31, wid = tid >> 5;
    const int qi = gridDim.x - 1 - blockIdx.x;     // heavy tiles first
    const int n = blockIdx.y, kvh = n >> 2;
    const int tq0 = qi * 128;
    const int ntiles = 2 * qi + 2;

    const __half* Qhg = Qhi + ((size_t)tq0 * NH + n) * HD;
    const __half* Qlg = Qlo + ((size_t)tq0 * NH + n) * HD;
    const __half* Kg  = Kv + (size_t)kvh * HD;
    const __half* Vg  = Vv + (size_t)kvh * HD;

    // ---- stage Qhi (into stage area) + Qlo (persistent) ----
    #pragma unroll
    for (int i = 0; i < 8; i++) {
        int c = tid + 256 * i;
        int row = c >> 4, c16 = c & 15;
        size_t go = (size_t)row * (NH * HD) + c16 * 8;
        CP16(uSt  + (uint32_t)row * SRB + c16 * 16, Qhg + go);
        CP16(uQlo + (uint32_t)row * SRB + c16 * 16, Qlg + go);
    }
    CP_COMMIT();
    CP_WAIT(0);
    __syncthreads();

    uint32_t qh[8][4];
    {
        const uint32_t qa = uSt + (uint32_t)(wid * 16 + (lane & 15)) * SRB
                          + (lane >> 4) * 16;
        #pragma unroll
        for (int dc = 0; dc < 8; dc++)
            LDSM4(qh[dc], qa + dc * 32);
    }
    __syncthreads();   // stage area free for KV

    const uint32_t qlA = uQlo + (uint32_t)(wid * 16 + (lane & 15)) * SRB
                       + (lane >> 4) * 16;
    // paired ldmatrix lane offsets
    const uint32_t kOff = (uint32_t)((lane >> 4) * 8 + (lane & 7)) * SRB
                        + ((lane >> 3) & 1) * 16;
    const uint32_t vOff = (uint32_t)(((lane >> 3) & 1) * 8 + (lane & 7)) * SRB
                        + ((lane >> 4) & 1) * 16;

    float o[16][4];
    #pragma unroll
    for (int i = 0; i < 16; i++)
        #pragma unroll
        for (int j = 0; j < 4; j++) o[i][j] = 0.f;
    float m0 = -1e30f, m1 = -1e30f, l0 = 0.f, l1 = 0.f;

    // preload tile 0
    #pragma unroll
    for (int i = 0; i < 4; i++) {
        int c = tid + 256 * i;
        int row = c >> 4, c16 = c & 15;
        size_t go = (size_t)row * (KH * HD) + c16 * 8;
        CP16(uSt + (uint32_t)row * SRB + c16 * 16, Kg + go);
        CP16(uSt + 64 * SRB + (uint32_t)row * SRB + c16 * 16, Vg + go);
    }
    CP_COMMIT();

    for (int t = 0; t < ntiles; t++) {
        CP_WAIT(0);
        __syncthreads();                 // tile t visible; all done reading stage (t+1)&1

        if (t + 1 < ntiles) {
            uint32_t st = uSt + ((t + 1) & 1) * (2 * 64 * SRB);
            const int s0 = (t + 1) * 64;
            #pragma unroll
            for (int i = 0; i < 4; i++) {
                int c = tid + 256 * i;
                int row = c >> 4, c16 = c & 15;
                size_t go = (size_t)(s0 + row) * (KH * HD) + c16 * 8;
                CP16(st + (uint32_t)row * SRB + c16 * 16, Kg + go);
                CP16(st + 64 * SRB + (uint32_t)row * SRB + c16 * 16, Vg + go);
            }
            CP_COMMIT();
        }

        const uint32_t uK = uSt + (t & 1) * (2 * 64 * SRB);
        const uint32_t uV = uK + 64 * SRB;

        // ---- S = Q K^T ----  (paired x4 non-trans K loads)
        float s[8][4];
        #pragma unroll
        for (int nt = 0; nt < 8; nt++)
            #pragma unroll
            for (int j = 0; j < 4; j++) s[nt][j] = 0.f;

        #pragma unroll
        for (int dc = 0; dc < 8; dc++) {
            uint32_t ql[4];
            LDSM4(ql, qlA + dc * 32);
            #pragma unroll
            for (int ntp = 0; ntp < 4; ntp++) {
                uint32_t r[4];
                LDSM4(r, uK + kOff + (uint32_t)ntp * 16 * SRB + dc * 32);
                uint32_t b0[2] = {r[0], r[1]}, b1[2] = {r[2], r[3]};
                MMAH(s[2*ntp],     qh[dc], b0);
                MMAH(s[2*ntp],     ql,     b0);
                MMAH(s[2*ntp + 1], qh[dc], b1);
                MMAH(s[2*ntp + 1], ql,     b1);
            }
        }

        // ---- causal mask ----
        if (t >= 2 * qi) {
            const int r0 = tq0 + wid * 16 + (lane >> 2);
            const int cB = t * 64 + (lane & 3) * 2;
            #pragma unroll
            for (int nt = 0; nt < 8; nt++) {
                int c0 = cB + nt * 8;
                if (c0     > r0)     s[nt][0] = -1e30f;
                if (c0 + 1 > r0)     s[nt][1] = -1e30f;
                if (c0     > r0 + 8) s[nt][2] = -1e30f;
                if (c0 + 1 > r0 + 8) s[nt][3] = -1e30f;
            }
        }

        // ---- online softmax ----
        float mr0 = -1e30f, mr1 = -1e30f;
        #pragma unroll
        for (int nt = 0; nt < 8; nt++) {
            mr0 = fmaxf(mr0, fmaxf(s[nt][0], s[nt][1]));
            mr1 = fmaxf(mr1, fmaxf(s[nt][2], s[nt][3]));
        }
        mr0 = fmaxf(mr0, __shfl_xor_sync(0xffffffffu, mr0, 1));
        mr0 = fmaxf(mr0, __shfl_xor_sync(0xffffffffu, mr0, 2));
        mr1 = fmaxf(mr1, __shfl_xor_sync(0xffffffffu, mr1, 1));
        mr1 = fmaxf(mr1, __shfl_xor_sync(0xffffffffu, mr1, 2));

        const float mn0 = fmaxf(m0, mr0), mn1 = fmaxf(m1, mr1);
        const float a0 = __expf(m0 - mn0), a1 = __expf(m1 - mn1);
        m0 = mn0; m1 = mn1;

        float ls0 = 0.f, ls1 = 0.f;
        #pragma unroll
        for (int nt = 0; nt < 8; nt++) {
            s[nt][0] = __expf(s[nt][0] - m0); ls0 += s[nt][0];
            s[nt][1] = __expf(s[nt][1] - m0); ls0 += s[nt][1];
            s[nt][2] = __expf(s[nt][2] - m1); ls1 += s[nt][2];
            s[nt][3] = __expf(s[nt][3] - m1); ls1 += s[nt][3];
        }
        ls0 += __shfl_xor_sync(0xffffffffu, ls0, 1);
        ls0 += __shfl_xor_sync(0xffffffffu, ls0, 2);
        ls1 += __shfl_xor_sync(0xffffffffu, ls1, 1);
        ls1 += __shfl_xor_sync(0xffffffffu, ls1, 2);
        l0 = l0 * a0 + ls0;
        l1 = l1 * a1 + ls1;

        #pragma unroll
        for (int i = 0; i < 16; i++) {
            o[i][0] *= a0; o[i][1] *= a0; o[i][2] *= a1; o[i][3] *= a1;
        }

        // ---- P fragments (hi/lo fp16) ----
        uint32_t phi[4][4], plo[4][4];
        #pragma unroll
        for (int kc = 0; kc < 4; kc++) {
            #pragma unroll
            for (int q = 0; q < 4; q++) {
                int nt = 2 * kc + (q >> 1);
                float f0 = s[nt][(q & 1) * 2], f1 = s[nt][(q & 1) * 2 + 1];
                __half2 h = __floats2half2_rn(f0, f1);
                float2 hf = __half22float2(h);
                __half2 l = __floats2half2_rn(f0 - hf.x, f1 - hf.y);
                phi[kc][q] = *(uint32_t*)&h;
                plo[kc][q] = *(uint32_t*)&l;
            }
        }

        // ---- O += P V ----  (paired x4 trans V loads)
        #pragma unroll
        for (int np = 0; np < 8; np++) {
            #pragma unroll
            for (int kc = 0; kc < 4; kc++) {
                uint32_t r[4];
                LDSM4T(r, uV + vOff + (uint32_t)kc * 16 * SRB + np * 32);
                uint32_t b0[2] = {r[0], r[1]}, b1[2] = {r[2], r[3]};
                MMAH(o[2*np],     phi[kc], b0);
                MMAH(o[2*np],     plo[kc], b0);
                MMAH(o[2*np + 1], phi[kc], b1);
                MMAH(o[2*np + 1], plo[kc], b1);
            }
        }
    }

    // ---- epilogue: O / l, write single fp16 ----
    const float i0 = 1.f / l0, i1 = 1.f / l1;
    const int r0 = tq0 + wid * 16 + (lane >> 2);
    const int cofs = (lane & 3) * 2;
    #pragma unroll
    for (int nt2 = 0; nt2 < 16; nt2++) {
        float v0 = o[nt2][0] * i0, v1 = o[nt2][1] * i0;
        float v2 = o[nt2][2] * i1, v3 = o[nt2][3] * i1;
        size_t p0 = ((size_t)r0 * NH + n) * HD + nt2 * 8 + cofs;
        size_t p1 = ((size_t)(r0 + 8) * NH + n) * HD + nt2 * 8 + cofs;
        *(__half2*)(Oh + p0) = __floats2half2_rn(v0, v1);
        *(__half2*)(Oh + p1) = __floats2half2_rn(v2, v3);
    }
}

// ====================== launch ======================
extern "C" void kernel_launch(void* const* d_in, const int* in_sizes, int n_in,
                              void* d_out, int out_size)
{
    const float* x   = (const float*)d_in[0];
    const int*   pos = (const int*)  d_in[1];
    const float* w_q = (const float*)d_in[2];
    const float* w_k = (const float*)d_in[3];
    const float* w_v = (const float*)d_in[4];
    const float* w_o = (const float*)d_in[5];
    float* out = (float*)d_out;

    float *q, *k;
    cudaGetSymbolAddress((void**)&q, g_q);
    cudaGetSymbolAddress((void**)&k, g_k);
    __half *xh, *xl, *aoh, *wqT, *wkT, *wvT, *woT, *qh, *ql, *kh, *vh;
    cudaGetSymbolAddress((void**)&xh,  g_xh);  cudaGetSymbolAddress((void**)&xl,  g_xl);
    cudaGetSymbolAddress((void**)&aoh, g_aoh);
    cudaGetSymbolAddress((void**)&wqT, g_wqT); cudaGetSymbolAddress((void**)&wkT, g_wkT);
    cudaGetSymbolAddress((void**)&wvT, g_wvT); cudaGetSymbolAddress((void**)&woT, g_woT);
    cudaGetSymbolAddress((void**)&qh,  g_qh);  cudaGetSymbolAddress((void**)&ql,  g_ql);
    cudaGetSymbolAddress((void**)&kh,  g_kh);  cudaGetSymbolAddress((void**)&vh,  g_vh);

    cudaFuncSetAttribute(gemm_qkv, cudaFuncAttributeMaxDynamicSharedMemorySize, GEMM_SMEM);
    cudaFuncSetAttribute(gemm_o,   cudaFuncAttributeMaxDynamicSharedMemorySize, GEMM_SMEM);
    cudaFuncSetAttribute(flash_h,  cudaFuncAttributeMaxDynamicSharedMemorySize, FL_SMEM);

    // operand prep (ordered so the 5th launch is the merged QKV GEMM for ncu -s 5)
    split_f32h<<<(TT*DD/4 + 255)/256, 256>>>(x, xh, xl, TT*DD/4);
    transT_f16<<<dim3(DD/32, DD/32),    256>>>(w_q, wqT, DD, DD);
    transT_f16<<<dim3(KH*HD/32, DD/32), 256>>>(w_k, wkT, DD, KH*HD);
    transT_f16<<<dim3(KH*HD/32, DD/32), 256>>>(w_v, wvT, DD, KH*HD);

    // merged QKV projection
    gemm_qkv<<<dim3(48, 16), 256, GEMM_SMEM>>>(xh, xl, wqT, wkT, wvT, q, k, vh);

    transT_f16<<<dim3(DD/32, DD/32),    256>>>(w_o, woT, DD, DD);

    // RoPE -> fp16
    rope_q<<<(TT*NH*64 + 255)/256, 256>>>(q, pos, qh, ql);
    rope_k<<<(TT*KH*64 + 255)/256, 256>>>(k, pos, kh);

    // causal GQA flash attention (HMMA) -> single fp16 attention output
    flash_h<<<dim3(TT/128, NH), 256, FL_SMEM>>>(qh, ql, kh, vh, aoh);

    // output projection (single-term)
    gemm_o<<<dim3(32, 16), 256, GEMM_SMEM>>>(aoh, woT, out);
}

// round 10
// speedup vs baseline: 1.4439x; 1.1129x over previous
#include <cuda_runtime.h>
#include <cuda_fp16.h>
#include <cstdint>
#include <math.h>

// Problem constants
#define TT 2048
#define DD 4096
#define NH 32
#define KH 8
#define HD 128
#define SCALE 0.08838834764831843f   // 1/sqrt(128)

// ====================== PTX helpers (base sm_103-legal only) ======================
__device__ __forceinline__ uint32_t smem_to_u32(const void* p) {
    uint32_t a;
    asm("{ .reg .u64 t; cvta.to.shared.u64 t, %1; cvt.u32.u64 %0, t; }" : "=r"(a) : "l"(p));
    return a;
}
#define CP16(sa, ga) \
    asm volatile("cp.async.cg.shared.global [%0], [%1], 16;" :: "r"(sa), "l"(ga) : "memory")
#define CP_COMMIT() asm volatile("cp.async.commit_group;" ::: "memory")
#define CP_WAIT(n)  asm volatile("cp.async.wait_group %0;" :: "n"(n) : "memory")
#define LDSM4(r, a) \
    asm volatile("ldmatrix.sync.aligned.m8n8.x4.shared.b16 {%0,%1,%2,%3}, [%4];" \
        : "=r"((r)[0]), "=r"((r)[1]), "=r"((r)[2]), "=r"((r)[3]) : "r"(a))
#define LDSM4T(r, a) \
    asm volatile("ldmatrix.sync.aligned.m8n8.x4.trans.shared.b16 {%0,%1,%2,%3}, [%4];" \
        : "=r"((r)[0]), "=r"((r)[1]), "=r"((r)[2]), "=r"((r)[3]) : "r"(a))
#define LDSM2(r, a) \
    asm volatile("ldmatrix.sync.aligned.m8n8.x2.shared.b16 {%0,%1}, [%2];" \
        : "=r"((r)[0]), "=r"((r)[1]) : "r"(a))
#define MMAH(d, a, b) \
    asm volatile("mma.sync.aligned.m16n8k16.row.col.f32.f16.f16.f32 " \
        "{%0,%1,%2,%3}, {%4,%5,%6,%7}, {%8,%9}, {%0,%1,%2,%3};" \
        : "+f"((d)[0]), "+f"((d)[1]), "+f"((d)[2]), "+f"((d)[3]) \
        : "r"((a)[0]), "r"((a)[1]), "r"((a)[2]), "r"((a)[3]), "r"((b)[0]), "r"((b)[1]))

// ====================== device scratch ======================
__device__ float  g_q [TT * NH * HD];
__device__ float  g_k [TT * KH * HD];

__device__ __half g_xh [TT * DD],  g_xl [TT * DD];
__device__ __half g_aoh[TT * DD];
__device__ __half g_wqT[DD * DD];                 // transposed [N][K] fp16
__device__ __half g_wkT[KH*HD * DD];
__device__ __half g_wvT[KH*HD * DD];
__device__ __half g_woT[DD * DD];
__device__ __half g_qh [TT * NH * HD], g_ql [TT * NH * HD];
__device__ __half g_kh [TT * KH * HD];
__device__ __half g_vh [TT * KH * HD];

// ====================== fp32 -> fp16 hi/lo split ======================
__global__ void split_f32h(const float* __restrict__ s, __half* __restrict__ hi,
                           __half* __restrict__ lo, int n4)
{
    int i = blockIdx.x * 256 + threadIdx.x;
    if (i >= n4) return;
    float4 f = ((const float4*)s)[i];
    float v[4] = {f.x, f.y, f.z, f.w};
    __align__(8) __half h[4], l[4];
    #pragma unroll
    for (int j = 0; j < 4; j++) {
        h[j] = __float2half_rn(v[j]);
        l[j] = __float2half_rn(v[j] - __half2float(h[j]));
    }
    *(uint2*)(hi + 4 * (size_t)i) = *(uint2*)h;
    *(uint2*)(lo + 4 * (size_t)i) = *(uint2*)l;
}

// transpose fp32 [R,C] -> single fp16 [C,R]
__global__ __launch_bounds__(256) void transT_f16(const float* __restrict__ s,
    __half* __restrict__ d, int R, int C)
{
    __shared__ float t[32][33];
    int bx = blockIdx.x * 32, by = blockIdx.y * 32;
    int tx = threadIdx.x & 31, ty = threadIdx.x >> 5;
    #pragma unroll
    for (int j = 0; j < 4; j++)
        t[ty + 8*j][tx] = s[(size_t)(by + ty + 8*j) * C + bx + tx];
    __syncthreads();
    #pragma unroll
    for (int j = 0; j < 4; j++)
        d[(size_t)(bx + ty + 8*j) * R + by + tx] = __float2half_rn(t[tx][ty + 8*j]);
}

// ====================== mma.sync GEMM core ======================
// 128x128 CTA tile, BK=32, 8 warps (2x4), warp tile 64x32, 3-stage, 1 barrier/stage.
// useLo (uniform per CTA): add Alo*B second term.
#define SROWB 80                       // smem row stride bytes (32 halves + pad)
#define TILE_B (128 * SROWB)           // 10240
#define STAGE_B (3 * TILE_B)           // Ahi | Alo | B   = 30720
#define GEMM_SMEM (3 * STAGE_B)        // 92160 (3 stages)

struct AccT { float a[4][4][4]; };

__device__ __forceinline__ void gemm_core(
    uint32_t sbase, const __half* pAh, const __half* pAl, const __half* pB,
    int Kd, AccT& A, const bool useLo)
{
    const int tid = threadIdx.x, lane = tid & 31, wid = tid >> 5;
    const int wm = wid >> 2, wn = wid & 3;
    const int lrow  = tid >> 2;
    const uint32_t lso = (tid & 3) * 16;
    const int lcolh = (tid & 3) * 8;

    const int nst = Kd >> 5;

    #pragma unroll
    for (int ps = 0; ps < 2; ps++) {         // prologue stages 0,1
        const int k0 = ps << 5;
        uint32_t st = sbase + ps * STAGE_B;
        #pragma unroll
        for (int i = 0; i < 2; i++) {
            int row = lrow + 64 * i;
            uint32_t so = st + (uint32_t)row * SROWB + lso;
            size_t go = (size_t)row * Kd + k0 + lcolh;
            CP16(so,            pAh + go);
            if (useLo) CP16(so + TILE_B, pAl + go);
            CP16(so + 2*TILE_B, pB  + go);
        }
        CP_COMMIT();
    }

    int sidx = 0;
    for (int s = 0; s < nst; s++) {
        if (s + 1 < nst) { CP_WAIT(1); } else { CP_WAIT(0); }
        __syncthreads();                     // single barrier per stage

        if (s + 2 < nst) {
            const int k0 = (s + 2) << 5;
            int lidx = sidx - 1; if (lidx < 0) lidx += 3;
            uint32_t st = sbase + lidx * STAGE_B;
            #pragma unroll
            for (int i = 0; i < 2; i++) {
                int row = lrow + 64 * i;
                uint32_t so = st + (uint32_t)row * SROWB + lso;
                size_t go = (size_t)row * Kd + k0 + lcolh;
                CP16(so,            pAh + go);
                if (useLo) CP16(so + TILE_B, pAl + go);
                CP16(so + 2*TILE_B, pB  + go);
            }
            CP_COMMIT();
        }

        uint32_t st = sbase + sidx * STAGE_B;
        const uint32_t aAddr = st + (uint32_t)(wm * 64 + (lane & 15)) * SROWB
                             + (lane >> 4) * 16;
        const uint32_t bAddr = st + 2 * TILE_B
                             + (uint32_t)(wn * 32 + (lane & 7)) * SROWB
                             + ((lane >> 3) & 1) * 16;

        #pragma unroll
        for (int kk = 0; kk < 2; kk++) {
            uint32_t ah[4][4], bb[4][2];
            #pragma unroll
            for (int mt = 0; mt < 4; mt++)
                LDSM4(ah[mt], aAddr + mt * 16 * SROWB + kk * 32);
            #pragma unroll
            for (int nt = 0; nt < 4; nt++)
                LDSM2(bb[nt], bAddr + nt * 8 * SROWB + kk * 32);
            #pragma unroll
            for (int mt = 0; mt < 4; mt++)
                #pragma unroll
                for (int nt = 0; nt < 4; nt++)
                    MMAH(A.a[mt][nt], ah[mt], bb[nt]);          // Ahi * B
            if (useLo) {
                uint32_t al[4][4];
                #pragma unroll
                for (int mt = 0; mt < 4; mt++)
                    LDSM4(al[mt], aAddr + TILE_B + mt * 16 * SROWB + kk * 32);
                #pragma unroll
                for (int mt = 0; mt < 4; mt++)
                    #pragma unroll
                    for (int nt = 0; nt < 4; nt++)
                        MMAH(A.a[mt][nt], al[mt], bb[nt]);      // Alo * B
            }
        }
        if (++sidx == 3) sidx = 0;
    }
}

// ---- merged QKV projection: grid (48, 16) ----
// Q blocks: two-term (feeds hi/lo split). K/V blocks: single-term (output is
// rounded to single fp16 anyway - lo term is below the quantization floor).
__global__ __launch_bounds__(256) void gemm_qkv(
    const __half* __restrict__ Ahi, const __half* __restrict__ Alo,
    const __half* __restrict__ WQ, const __half* __restrict__ WK,
    const __half* __restrict__ WV,
    float* __restrict__ Cq, float* __restrict__ Ck, __half* __restrict__ Cv)
{
    extern __shared__ char smraw[];
    const uint32_t sbase = smem_to_u32(smraw);
    const int bx = blockIdx.x;
    const int Kd = DD;

    const __half* pB;
    int bn, kind;       // kind 0=q(f32,2-term), 1=k(f32,1-term), 2=v(f16,1-term)
    if (bx < 32)      { pB = WQ; bn = bx;      kind = 0; }
    else if (bx < 40) { pB = WK; bn = bx - 32; kind = 1; }
    else              { pB = WV; bn = bx - 40; kind = 2; }
    pB += (size_t)bn * 128 * Kd;

    AccT A;
    #pragma unroll
    for (int mt = 0; mt < 4; mt++)
        #pragma unroll
        for (int nt = 0; nt < 4; nt++)
            #pragma unroll
            for (int q = 0; q < 4; q++) A.a[mt][nt][q] = 0.f;

    gemm_core(sbase,
              Ahi + (size_t)blockIdx.y * 128 * Kd,
              Alo + (size_t)blockIdx.y * 128 * Kd, pB, Kd, A, kind == 0);

    const int lane = threadIdx.x & 31, wid = threadIdx.x >> 5;
    const int wm = wid >> 2, wn = wid & 3;
    const int rb = blockIdx.y * 128 + wm * 64 + (lane >> 2);
    const int cbl = bn * 128 + wn * 32 + (lane & 3) * 2;
    const int Nloc = (kind == 0) ? NH * HD : KH * HD;

    #pragma unroll
    for (int mt = 0; mt < 4; mt++)
        #pragma unroll
        for (int nt = 0; nt < 4; nt++) {
            const int row = rb + mt * 16;
            const int col = cbl + nt * 8;
            if (kind == 2) {
                *(__half2*)(Cv + (size_t)row * Nloc + col) =
                    __floats2half2_rn(A.a[mt][nt][0], A.a[mt][nt][1]);
                *(__half2*)(Cv + (size_t)(row + 8) * Nloc + col) =
                    __floats2half2_rn(A.a[mt][nt][2], A.a[mt][nt][3]);
            } else {
                float* C = (kind == 0) ? Cq : Ck;
                *(float2*)(C + (size_t)row * Nloc + col) =
                    make_float2(A.a[mt][nt][0], A.a[mt][nt][1]);
                *(float2*)(C + (size_t)(row + 8) * Nloc + col) =
                    make_float2(A.a[mt][nt][2], A.a[mt][nt][3]);
            }
        }
}

// ---- o-proj: single-term A (ao fp16), C fp32, grid (32, 16) ----
__global__ __launch_bounds__(256) void gemm_o(
    const __half* __restrict__ Ah, const __half* __restrict__ BT,
    float* __restrict__ C)
{
    extern __shared__ char smraw[];
    const uint32_t sbase = smem_to_u32(smraw);
    const int Kd = DD, N = DD;

    AccT A;
    #pragma unroll
    for (int mt = 0; mt < 4; mt++)
        #pragma unroll
        for (int nt = 0; nt < 4; nt++)
            #pragma unroll
            for (int q = 0; q < 4; q++) A.a[mt][nt][q] = 0.f;

    gemm_core(sbase,
              Ah + (size_t)blockIdx.y * 128 * Kd, (const __half*)0,
              BT + (size_t)blockIdx.x * 128 * Kd, Kd, A, false);

    const int lane = threadIdx.x & 31, wid = threadIdx.x >> 5;
    const int wm = wid >> 2, wn = wid & 3;
    const int rb = blockIdx.y * 128 + wm * 64 + (lane >> 2);
    const int cb = blockIdx.x * 128 + wn * 32 + (lane & 3) * 2;
    #pragma unroll
    for (int mt = 0; mt < 4; mt++)
        #pragma unroll
        for (int nt = 0; nt < 4; nt++) {
            const int row = rb + mt * 16;
            const int col = cb + nt * 8;
            *(float2*)(C + (size_t)row * N + col) =
                make_float2(A.a[mt][nt][0], A.a[mt][nt][1]);
            *(float2*)(C + (size_t)(row + 8) * N + col) =
                make_float2(A.a[mt][nt][2], A.a[mt][nt][3]);
        }
}

// ====================== RoPE + fp16 outputs ======================
__global__ void rope_q(const float* __restrict__ src, const int* __restrict__ pos,
                       __half* __restrict__ qh, __half* __restrict__ ql)
{
    int idx = blockIdx.x * 256 + threadIdx.x;
    if (idx >= TT * NH * 64) return;
    int hh = idx & 63;
    int h  = (idx >> 6) % NH;
    int t  = idx / (64 * NH);

    float e   = (float)hh * (1.0f / 64.0f);
    float inv = 1.0f / powf(10000.0f, e);
    float ang = (float)pos[t] * inv;
    float s, c;
    sincosf(ang, &s, &c);

    size_t base = ((size_t)t * NH + h) * HD + hh;
    float x1 = src[base], x2 = src[base + 64];
    float y1 = (x1 * c - x2 * s) * SCALE;
    float y2 = (x2 * c + x1 * s) * SCALE;
    __half h1 = __float2half_rn(y1), h2 = __float2half_rn(y2);
    qh[base]      = h1;  ql[base]      = __float2half_rn(y1 - __half2float(h1));
    qh[base + 64] = h2;  ql[base + 64] = __float2half_rn(y2 - __half2float(h2));
}

__global__ void rope_k(const float* __restrict__ src, const int* __restrict__ pos,
                       __half* __restrict__ kh)
{
    int idx = blockIdx.x * 256 + threadIdx.x;
    if (idx >= TT * KH * 64) return;
    int hh = idx & 63;
    int h  = (idx >> 6) % KH;
    int t  = idx / (64 * KH);

    float e   = (float)hh * (1.0f / 64.0f);
    float inv = 1.0f / powf(10000.0f, e);
    float ang = (float)pos[t] * inv;
    float s, c;
    sincosf(ang, &s, &c);

    size_t base = ((size_t)t * KH + h) * HD + hh;
    float x1 = src[base], x2 = src[base + 64];
    kh[base]      = __float2half_rn(x1 * c - x2 * s);
    kh[base + 64] = __float2half_rn(x2 * c + x1 * s);
}

// ====================== HMMA flash attention (causal, GQA) ======================
// CTA: 128 q rows x 1 head, 8 warps (16 q rows each). KV tiles of 64.
#define SRH 136
#define SRB 272
#define FL_SMEM ((128 * SRH + 4 * 64 * SRH) * 2)   // Qlo + 2 stages of (K,V)

__global__ __launch_bounds__(256) void flash_h(
    const __half* __restrict__ Qhi, const __half* __restrict__ Qlo,
    const __half* __restrict__ Kv,  const __half* __restrict__ Vv,
    __half* __restrict__ Oh)
{
    extern __shared__ char fsm[];
    const uint32_t uQlo = smem_to_u32(fsm);
    const uint32_t uSt  = uQlo + 128 * SRB;

    const int tid = threadIdx.x, lane = tid & 31, wid = tid >> 5;
    const int qi = gridDim.x - 1 - blockIdx.x;     // heavy tiles first
    const int n = blockIdx.y, kvh = n >> 2;
    const int tq0 = qi * 128;
    const int ntiles = 2 * qi + 2;

    const __half* Qhg = Qhi + ((size_t)tq0 * NH + n) * HD;
    const __half* Qlg = Qlo + ((size_t)tq0 * NH + n) * HD;
    const __half* Kg  = Kv + (size_t)kvh * HD;
    const __half* Vg  = Vv + (size_t)kvh * HD;

    // ---- stage Qhi (into stage area) + Qlo (persistent) ----
    #pragma unroll
    for (int i = 0; i < 8; i++) {
        int c = tid + 256 * i;
        int row = c >> 4, c16 = c & 15;
        size_t go = (size_t)row * (NH * HD) + c16 * 8;
        CP16(uSt  + (uint32_t)row * SRB + c16 * 16, Qhg + go);
        CP16(uQlo + (uint32_t)row * SRB + c16 * 16, Qlg + go);
    }
    CP_COMMIT();
    CP_WAIT(0);
    __syncthreads();

    uint32_t qh[8][4];
    {
        const uint32_t qa = uSt + (uint32_t)(wid * 16 + (lane & 15)) * SRB
                          + (lane >> 4) * 16;
        #pragma unroll
        for (int dc = 0; dc < 8; dc++)
            LDSM4(qh[dc], qa + dc * 32);
    }
    __syncthreads();   // stage area free for KV

    const uint32_t qlA = uQlo + (uint32_t)(wid * 16 + (lane & 15)) * SRB
                       + (lane >> 4) * 16;
    // paired ldmatrix lane offsets
    const uint32_t kOff = (uint32_t)((lane >> 4) * 8 + (lane & 7)) * SRB
                        + ((lane >> 3) & 1) * 16;
    const uint32_t vOff = (uint32_t)(((lane >> 3) & 1) * 8 + (lane & 7)) * SRB
                        + ((lane >> 4) & 1) * 16;

    float o[16][4];
    #pragma unroll
    for (int i = 0; i < 16; i++)
        #pragma unroll
        for (int j = 0; j < 4; j++) o[i][j] = 0.f;
    float m0 = -1e30f, m1 = -1e30f, l0 = 0.f, l1 = 0.f;

    // preload tile 0
    #pragma unroll
    for (int i = 0; i < 4; i++) {
        int c = tid + 256 * i;
        int row = c >> 4, c16 = c & 15;
        size_t go = (size_t)row * (KH * HD) + c16 * 8;
        CP16(uSt + (uint32_t)row * SRB + c16 * 16, Kg + go);
        CP16(uSt + 64 * SRB + (uint32_t)row * SRB + c16 * 16, Vg + go);
    }
    CP_COMMIT();

    for (int t = 0; t < ntiles; t++) {
        CP_WAIT(0);
        __syncthreads();                 // tile t visible; all done reading stage (t+1)&1

        if (t + 1 < ntiles) {
            uint32_t st = uSt + ((t + 1) & 1) * (2 * 64 * SRB);
            const int s0 = (t + 1) * 64;
            #pragma unroll
            for (int i = 0; i < 4; i++) {
                int c = tid + 256 * i;
                int row = c >> 4, c16 = c & 15;
                size_t go = (size_t)(s0 + row) * (KH * HD) + c16 * 8;
                CP16(st + (uint32_t)row * SRB + c16 * 16, Kg + go);
                CP16(st + 64 * SRB + (uint32_t)row * SRB + c16 * 16, Vg + go);
            }
            CP_COMMIT();
        }

        const uint32_t uK = uSt + (t & 1) * (2 * 64 * SRB);
        const uint32_t uV = uK + 64 * SRB;

        // ---- S = Q K^T ----  (paired x4 non-trans K loads, Qhi+Qlo terms)
        float s[8][4];
        #pragma unroll
        for (int nt = 0; nt < 8; nt++)
            #pragma unroll
            for (int j = 0; j < 4; j++) s[nt][j] = 0.f;

        #pragma unroll
        for (int dc = 0; dc < 8; dc++) {
            uint32_t ql[4];
            LDSM4(ql, qlA + dc * 32);
            #pragma unroll
            for (int ntp = 0; ntp < 4; ntp++) {
                uint32_t r[4];
                LDSM4(r, uK + kOff + (uint32_t)ntp * 16 * SRB + dc * 32);
                uint32_t b0[2] = {r[0], r[1]}, b1[2] = {r[2], r[3]};
                MMAH(s[2*ntp],     qh[dc], b0);
                MMAH(s[2*ntp],     ql,     b0);
                MMAH(s[2*ntp + 1], qh[dc], b1);
                MMAH(s[2*ntp + 1], ql,     b1);
            }
        }

        // ---- causal mask ----
        if (t >= 2 * qi) {
            const int r0 = tq0 + wid * 16 + (lane >> 2);
            const int cB = t * 64 + (lane & 3) * 2;
            #pragma unroll
            for (int nt = 0; nt < 8; nt++) {
                int c0 = cB + nt * 8;
                if (c0     > r0)     s[nt][0] = -1e30f;
                if (c0 + 1 > r0)     s[nt][1] = -1e30f;
                if (c0     > r0 + 8) s[nt][2] = -1e30f;
                if (c0 + 1 > r0 + 8) s[nt][3] = -1e30f;
            }
        }

        // ---- online softmax ----
        float mr0 = -1e30f, mr1 = -1e30f;
        #pragma unroll
        for (int nt = 0; nt < 8; nt++) {
            mr0 = fmaxf(mr0, fmaxf(s[nt][0], s[nt][1]));
            mr1 = fmaxf(mr1, fmaxf(s[nt][2], s[nt][3]));
        }
        mr0 = fmaxf(mr0, __shfl_xor_sync(0xffffffffu, mr0, 1));
        mr0 = fmaxf(mr0, __shfl_xor_sync(0xffffffffu, mr0, 2));
        mr1 = fmaxf(mr1, __shfl_xor_sync(0xffffffffu, mr1, 1));
        mr1 = fmaxf(mr1, __shfl_xor_sync(0xffffffffu, mr1, 2));

        const float mn0 = fmaxf(m0, mr0), mn1 = fmaxf(m1, mr1);
        const float a0 = __expf(m0 - mn0), a1 = __expf(m1 - mn1);
        m0 = mn0; m1 = mn1;

        float ls0 = 0.f, ls1 = 0.f;
        #pragma unroll
        for (int nt = 0; nt < 8; nt++) {
            s[nt][0] = __expf(s[nt][0] - m0); ls0 += s[nt][0];
            s[nt][1] = __expf(s[nt][1] - m0); ls0 += s[nt][1];
            s[nt][2] = __expf(s[nt][2] - m1); ls1 += s[nt][2];
            s[nt][3] = __expf(s[nt][3] - m1); ls1 += s[nt][3];
        }
        ls0 += __shfl_xor_sync(0xffffffffu, ls0, 1);
        ls0 += __shfl_xor_sync(0xffffffffu, ls0, 2);
        ls1 += __shfl_xor_sync(0xffffffffu, ls1, 1);
        ls1 += __shfl_xor_sync(0xffffffffu, ls1, 2);
        l0 = l0 * a0 + ls0;
        l1 = l1 * a1 + ls1;

        #pragma unroll
        for (int i = 0; i < 16; i++) {
            o[i][0] *= a0; o[i][1] *= a0; o[i][2] *= a1; o[i][3] *= a1;
        }

        // ---- P fragments (single fp16 - output is fp16-rounded anyway) ----
        uint32_t phi[4][4];
        #pragma unroll
        for (int kc = 0; kc < 4; kc++) {
            #pragma unroll
            for (int q = 0; q < 4; q++) {
                int nt = 2 * kc + (q >> 1);
                __half2 h = __floats2half2_rn(s[nt][(q & 1) * 2],
                                              s[nt][(q & 1) * 2 + 1]);
                phi[kc][q] = *(uint32_t*)&h;
            }
        }

        // ---- O += P V ----  (paired x4 trans V loads, single P term)
        #pragma unroll
        for (int np = 0; np < 8; np++) {
            #pragma unroll
            for (int kc = 0; kc < 4; kc++) {
                uint32_t r[4];
                LDSM4T(r, uV + vOff + (uint32_t)kc * 16 * SRB + np * 32);
                uint32_t b0[2] = {r[0], r[1]}, b1[2] = {r[2], r[3]};
                MMAH(o[2*np],     phi[kc], b0);
                MMAH(o[2*np + 1], phi[kc], b1);
            }
        }
    }

    // ---- epilogue: O / l, write single fp16 ----
    const float i0 = 1.f / l0, i1 = 1.f / l1;
    const int r0 = tq0 + wid * 16 + (lane >> 2);
    const int cofs = (lane & 3) * 2;
    #pragma unroll
    for (int nt2 = 0; nt2 < 16; nt2++) {
        float v0 = o[nt2][0] * i0, v1 = o[nt2][1] * i0;
        float v2 = o[nt2][2] * i1, v3 = o[nt2][3] * i1;
        size_t p0 = ((size_t)r0 * NH + n) * HD + nt2 * 8 + cofs;
        size_t p1 = ((size_t)(r0 + 8) * NH + n) * HD + nt2 * 8 + cofs;
        *(__half2*)(Oh + p0) = __floats2half2_rn(v0, v1);
        *(__half2*)(Oh + p1) = __floats2half2_rn(v2, v3);
    }
}

// ====================== launch ======================
extern "C" void kernel_launch(void* const* d_in, const int* in_sizes, int n_in,
                              void* d_out, int out_size)
{
    const float* x   = (const float*)d_in[0];
    const int*   pos = (const int*)  d_in[1];
    const float* w_q = (const float*)d_in[2];
    const float* w_k = (const float*)d_in[3];
    const float* w_v = (const float*)d_in[4];
    const float* w_o = (const float*)d_in[5];
    float* out = (float*)d_out;

    float *q, *k;
    cudaGetSymbolAddress((void**)&q, g_q);
    cudaGetSymbolAddress((void**)&k, g_k);
    __half *xh, *xl, *aoh, *wqT, *wkT, *wvT, *woT, *qh, *ql, *kh, *vh;
    cudaGetSymbolAddress((void**)&xh,  g_xh);  cudaGetSymbolAddress((void**)&xl,  g_xl);
    cudaGetSymbolAddress((void**)&aoh, g_aoh);
    cudaGetSymbolAddress((void**)&wqT, g_wqT); cudaGetSymbolAddress((void**)&wkT, g_wkT);
    cudaGetSymbolAddress((void**)&wvT, g_wvT); cudaGetSymbolAddress((void**)&woT, g_woT);
    cudaGetSymbolAddress((void**)&qh,  g_qh);  cudaGetSymbolAddress((void**)&ql,  g_ql);
    cudaGetSymbolAddress((void**)&kh,  g_kh);  cudaGetSymbolAddress((void**)&vh,  g_vh);

    cudaFuncSetAttribute(gemm_qkv, cudaFuncAttributeMaxDynamicSharedMemorySize, GEMM_SMEM);
    cudaFuncSetAttribute(gemm_o,   cudaFuncAttributeMaxDynamicSharedMemorySize, GEMM_SMEM);
    cudaFuncSetAttribute(flash_h,  cudaFuncAttributeMaxDynamicSharedMemorySize, FL_SMEM);

    // operand prep (ordered so the 5th launch is the merged QKV GEMM for ncu -s 5)
    split_f32h<<<(TT*DD/4 + 255)/256, 256>>>(x, xh, xl, TT*DD/4);
    transT_f16<<<dim3(DD/32, DD/32),    256>>>(w_q, wqT, DD, DD);
    transT_f16<<<dim3(KH*HD/32, DD/32), 256>>>(w_k, wkT, DD, KH*HD);
    transT_f16<<<dim3(KH*HD/32, DD/32), 256>>>(w_v, wvT, DD, KH*HD);

    // merged QKV projection (Q 2-term, K/V 1-term)
    gemm_qkv<<<dim3(48, 16), 256, GEMM_SMEM>>>(xh, xl, wqT, wkT, wvT, q, k, vh);

    transT_f16<<<dim3(DD/32, DD/32),    256>>>(w_o, woT, DD, DD);

    // RoPE -> fp16
    rope_q<<<(TT*NH*64 + 255)/256, 256>>>(q, pos, qh, ql);
    rope_k<<<(TT*KH*64 + 255)/256, 256>>>(k, pos, kh);

    // causal GQA flash attention (HMMA) -> single fp16 attention output
    flash_h<<<dim3(TT/128, NH), 256, FL_SMEM>>>(qh, ql, kh, vh, aoh);

    // output projection (single-term)
    gemm_o<<<dim3(32, 16), 256, GEMM_SMEM>>>(aoh, woT, out);
}

// round 11
// speedup vs baseline: 1.7947x; 1.2430x over previous
#include <cuda_runtime.h>
#include <cuda_fp16.h>
#include <cstdint>
#include <math.h>

// Problem constants
#define TT 2048
#define DD 4096
#define NH 32
#define KH 8
#define HD 128
#define SCALE 0.08838834764831843f   // 1/sqrt(128)

// ====================== PTX helpers (base sm_103-legal only) ======================
__device__ __forceinline__ uint32_t smem_to_u32(const void* p) {
    uint32_t a;
    asm("{ .reg .u64 t; cvta.to.shared.u64 t, %1; cvt.u32.u64 %0, t; }" : "=r"(a) : "l"(p));
    return a;
}
#define CP16(sa, ga) \
    asm volatile("cp.async.cg.shared.global [%0], [%1], 16;" :: "r"(sa), "l"(ga) : "memory")
#define CP_COMMIT() asm volatile("cp.async.commit_group;" ::: "memory")
#define CP_WAIT(n)  asm volatile("cp.async.wait_group %0;" :: "n"(n) : "memory")
#define LDSM4(r, a) \
    asm volatile("ldmatrix.sync.aligned.m8n8.x4.shared.b16 {%0,%1,%2,%3}, [%4];" \
        : "=r"((r)[0]), "=r"((r)[1]), "=r"((r)[2]), "=r"((r)[3]) : "r"(a))
#define LDSM4T(r, a) \
    asm volatile("ldmatrix.sync.aligned.m8n8.x4.trans.shared.b16 {%0,%1,%2,%3}, [%4];" \
        : "=r"((r)[0]), "=r"((r)[1]), "=r"((r)[2]), "=r"((r)[3]) : "r"(a))
#define LDSM2(r, a) \
    asm volatile("ldmatrix.sync.aligned.m8n8.x2.shared.b16 {%0,%1}, [%2];" \
        : "=r"((r)[0]), "=r"((r)[1]) : "r"(a))
#define MMAH(d, a, b) \
    asm volatile("mma.sync.aligned.m16n8k16.row.col.f32.f16.f16.f32 " \
        "{%0,%1,%2,%3}, {%4,%5,%6,%7}, {%8,%9}, {%0,%1,%2,%3};" \
        : "+f"((d)[0]), "+f"((d)[1]), "+f"((d)[2]), "+f"((d)[3]) \
        : "r"((a)[0]), "r"((a)[1]), "r"((a)[2]), "r"((a)[3]), "r"((b)[0]), "r"((b)[1]))

// ====================== device scratch ======================
__device__ float  g_q [TT * NH * HD];
__device__ float  g_k [TT * KH * HD];

__device__ __half g_xh [TT * DD];
__device__ __half g_aoh[TT * DD];
__device__ __half g_wqT[DD * DD];                 // transposed [N][K] fp16
__device__ __half g_wkT[KH*HD * DD];
__device__ __half g_wvT[KH*HD * DD];
__device__ __half g_woT[DD * DD];
__device__ __half g_qh [TT * NH * HD];
__device__ __half g_kh [TT * KH * HD];
__device__ __half g_vh [TT * KH * HD];

// ====================== fp32 -> fp16 convert ======================
__global__ void conv_h(const float* __restrict__ s, __half* __restrict__ d, int n4)
{
    int i = blockIdx.x * 256 + threadIdx.x;
    if (i >= n4) return;
    float4 f = ((const float4*)s)[i];
    __align__(8) __half h[4] = {__float2half_rn(f.x), __float2half_rn(f.y),
                                __float2half_rn(f.z), __float2half_rn(f.w)};
    *(uint2*)(d + 4 * (size_t)i) = *(uint2*)h;
}

// transpose fp32 [R,C] -> single fp16 [C,R]
__global__ __launch_bounds__(256) void transT_f16(const float* __restrict__ s,
    __half* __restrict__ d, int R, int C)
{
    __shared__ float t[32][33];
    int bx = blockIdx.x * 32, by = blockIdx.y * 32;
    int tx = threadIdx.x & 31, ty = threadIdx.x >> 5;
    #pragma unroll
    for (int j = 0; j < 4; j++)
        t[ty + 8*j][tx] = s[(size_t)(by + ty + 8*j) * C + bx + tx];
    __syncthreads();
    #pragma unroll
    for (int j = 0; j < 4; j++)
        d[(size_t)(bx + ty + 8*j) * R + by + tx] = __float2half_rn(t[tx][ty + 8*j]);
}

// ====================== mma.sync GEMM core (single-term) ======================
// 128x128 CTA tile, BK=32, 8 warps (2x4), warp tile 64x32, 3-stage, 1 barrier/stage.
#define SROWB 80                       // smem row stride bytes (32 halves + pad)
#define TILE_B (128 * SROWB)           // 10240
#define STAGE_B (2 * TILE_B)           // A | B = 20480
#define GEMM_SMEM (3 * STAGE_B)        // 61440 (3 stages)

struct AccT { float a[4][4][4]; };

__device__ __forceinline__ void gemm_core(
    uint32_t sbase, const __half* pA, const __half* pB, int Kd, AccT& A)
{
    const int tid = threadIdx.x, lane = tid & 31, wid = tid >> 5;
    const int wm = wid >> 2, wn = wid & 3;
    const int lrow  = tid >> 2;
    const uint32_t lso = (tid & 3) * 16;
    const int lcolh = (tid & 3) * 8;

    const int nst = Kd >> 5;

    #pragma unroll
    for (int ps = 0; ps < 2; ps++) {         // prologue stages 0,1
        const int k0 = ps << 5;
        uint32_t st = sbase + ps * STAGE_B;
        #pragma unroll
        for (int i = 0; i < 2; i++) {
            int row = lrow + 64 * i;
            uint32_t so = st + (uint32_t)row * SROWB + lso;
            size_t go = (size_t)row * Kd + k0 + lcolh;
            CP16(so,          pA + go);
            CP16(so + TILE_B, pB + go);
        }
        CP_COMMIT();
    }

    int sidx = 0;
    for (int s = 0; s < nst; s++) {
        if (s + 1 < nst) { CP_WAIT(1); } else { CP_WAIT(0); }
        __syncthreads();                     // single barrier per stage

        if (s + 2 < nst) {
            const int k0 = (s + 2) << 5;
            int lidx = sidx - 1; if (lidx < 0) lidx += 3;
            uint32_t st = sbase + lidx * STAGE_B;
            #pragma unroll
            for (int i = 0; i < 2; i++) {
                int row = lrow + 64 * i;
                uint32_t so = st + (uint32_t)row * SROWB + lso;
                size_t go = (size_t)row * Kd + k0 + lcolh;
                CP16(so,          pA + go);
                CP16(so + TILE_B, pB + go);
            }
            CP_COMMIT();
        }

        uint32_t st = sbase + sidx * STAGE_B;
        const uint32_t aAddr = st + (uint32_t)(wm * 64 + (lane & 15)) * SROWB
                             + (lane >> 4) * 16;
        const uint32_t bAddr = st + TILE_B
                             + (uint32_t)(wn * 32 + (lane & 7)) * SROWB
                             + ((lane >> 3) & 1) * 16;

        #pragma unroll
        for (int kk = 0; kk < 2; kk++) {
            uint32_t ah[4][4], bb[4][2];
            #pragma unroll
            for (int mt = 0; mt < 4; mt++)
                LDSM4(ah[mt], aAddr + mt * 16 * SROWB + kk * 32);
            #pragma unroll
            for (int nt = 0; nt < 4; nt++)
                LDSM2(bb[nt], bAddr + nt * 8 * SROWB + kk * 32);
            #pragma unroll
            for (int mt = 0; mt < 4; mt++)
                #pragma unroll
                for (int nt = 0; nt < 4; nt++)
                    MMAH(A.a[mt][nt], ah[mt], bb[nt]);
        }
        if (++sidx == 3) sidx = 0;
    }
}

// ---- merged QKV projection: grid (48, 16), all single-term ----
__global__ __launch_bounds__(256) void gemm_qkv(
    const __half* __restrict__ Ah,
    const __half* __restrict__ WQ, const __half* __restrict__ WK,
    const __half* __restrict__ WV,
    float* __restrict__ Cq, float* __restrict__ Ck, __half* __restrict__ Cv)
{
    extern __shared__ char smraw[];
    const uint32_t sbase = smem_to_u32(smraw);
    const int bx = blockIdx.x;
    const int Kd = DD;

    const __half* pB;
    int bn, kind;       // kind 0=q(f32), 1=k(f32), 2=v(f16)
    if (bx < 32)      { pB = WQ; bn = bx;      kind = 0; }
    else if (bx < 40) { pB = WK; bn = bx - 32; kind = 1; }
    else              { pB = WV; bn = bx - 40; kind = 2; }
    pB += (size_t)bn * 128 * Kd;

    AccT A;
    #pragma unroll
    for (int mt = 0; mt < 4; mt++)
        #pragma unroll
        for (int nt = 0; nt < 4; nt++)
            #pragma unroll
            for (int q = 0; q < 4; q++) A.a[mt][nt][q] = 0.f;

    gemm_core(sbase, Ah + (size_t)blockIdx.y * 128 * Kd, pB, Kd, A);

    const int lane = threadIdx.x & 31, wid = threadIdx.x >> 5;
    const int wm = wid >> 2, wn = wid & 3;
    const int rb = blockIdx.y * 128 + wm * 64 + (lane >> 2);
    const int cbl = bn * 128 + wn * 32 + (lane & 3) * 2;
    const int Nloc = (kind == 0) ? NH * HD : KH * HD;

    #pragma unroll
    for (int mt = 0; mt < 4; mt++)
        #pragma unroll
        for (int nt = 0; nt < 4; nt++) {
            const int row = rb + mt * 16;
            const int col = cbl + nt * 8;
            if (kind == 2) {
                *(__half2*)(Cv + (size_t)row * Nloc + col) =
                    __floats2half2_rn(A.a[mt][nt][0], A.a[mt][nt][1]);
                *(__half2*)(Cv + (size_t)(row + 8) * Nloc + col) =
                    __floats2half2_rn(A.a[mt][nt][2], A.a[mt][nt][3]);
            } else {
                float* C = (kind == 0) ? Cq : Ck;
                *(float2*)(C + (size_t)row * Nloc + col) =
                    make_float2(A.a[mt][nt][0], A.a[mt][nt][1]);
                *(float2*)(C + (size_t)(row + 8) * Nloc + col) =
                    make_float2(A.a[mt][nt][2], A.a[mt][nt][3]);
            }
        }
}

// ---- o-proj: single-term A (ao fp16), C fp32, grid (32, 16) ----
__global__ __launch_bounds__(256) void gemm_o(
    const __half* __restrict__ Ah, const __half* __restrict__ BT,
    float* __restrict__ C)
{
    extern __shared__ char smraw[];
    const uint32_t sbase = smem_to_u32(smraw);
    const int Kd = DD, N = DD;

    AccT A;
    #pragma unroll
    for (int mt = 0; mt < 4; mt++)
        #pragma unroll
        for (int nt = 0; nt < 4; nt++)
            #pragma unroll
            for (int q = 0; q < 4; q++) A.a[mt][nt][q] = 0.f;

    gemm_core(sbase, Ah + (size_t)blockIdx.y * 128 * Kd,
              BT + (size_t)blockIdx.x * 128 * Kd, Kd, A);

    const int lane = threadIdx.x & 31, wid = threadIdx.x >> 5;
    const int wm = wid >> 2, wn = wid & 3;
    const int rb = blockIdx.y * 128 + wm * 64 + (lane >> 2);
    const int cb = blockIdx.x * 128 + wn * 32 + (lane & 3) * 2;
    #pragma unroll
    for (int mt = 0; mt < 4; mt++)
        #pragma unroll
        for (int nt = 0; nt < 4; nt++) {
            const int row = rb + mt * 16;
            const int col = cb + nt * 8;
            *(float2*)(C + (size_t)row * N + col) =
                make_float2(A.a[mt][nt][0], A.a[mt][nt][1]);
            *(float2*)(C + (size_t)(row + 8) * N + col) =
                make_float2(A.a[mt][nt][2], A.a[mt][nt][3]);
        }
}

// ====================== RoPE -> single fp16 ======================
__global__ void rope_h(const float* __restrict__ src, const int* __restrict__ pos,
                       __half* __restrict__ dst, int heads, float scale)
{
    int idx = blockIdx.x * 256 + threadIdx.x;
    if (idx >= TT * heads * 64) return;
    int hh = idx & 63;
    int h  = (idx >> 6) % heads;
    int t  = idx / (64 * heads);

    float e   = (float)hh * (1.0f / 64.0f);
    float inv = 1.0f / powf(10000.0f, e);
    float ang = (float)pos[t] * inv;
    float s, c;
    sincosf(ang, &s, &c);

    size_t base = ((size_t)t * heads + h) * HD + hh;
    float x1 = src[base], x2 = src[base + 64];
    dst[base]      = __float2half_rn((x1 * c - x2 * s) * scale);
    dst[base + 64] = __float2half_rn((x2 * c + x1 * s) * scale);
}

// ====================== HMMA flash attention (causal, GQA) ======================
// CTA: 128 q rows x 1 head, 8 warps (16 q rows each). KV tiles of 64.
// All operands single fp16; Q frags persistent in registers.
#define SRH 136
#define SRB 272
#define FL_SMEM ((4 * 64 * SRH) * 2)   // 2 stages of (K,V) = 69632

__global__ __launch_bounds__(256) void flash_h(
    const __half* __restrict__ Qv, const __half* __restrict__ Kv,
    const __half* __restrict__ Vv, __half* __restrict__ Oh)
{
    extern __shared__ char fsm[];
    const uint32_t uSt = smem_to_u32(fsm);

    const int tid = threadIdx.x, lane = tid & 31, wid = tid >> 5;
    const int qi = gridDim.x - 1 - blockIdx.x;     // heavy tiles first
    const int n = blockIdx.y, kvh = n >> 2;
    const int tq0 = qi * 128;
    const int ntiles = 2 * qi + 2;

    const __half* Qg = Qv + ((size_t)tq0 * NH + n) * HD;
    const __half* Kg = Kv + (size_t)kvh * HD;
    const __half* Vg = Vv + (size_t)kvh * HD;

    // ---- stage Q into stage-0 area (128 rows x SRB = whole stage), read frags ----
    #pragma unroll
    for (int i = 0; i < 8; i++) {
        int c = tid + 256 * i;
        int row = c >> 4, c16 = c & 15;
        CP16(uSt + (uint32_t)row * SRB + c16 * 16,
             Qg + (size_t)row * (NH * HD) + c16 * 8);
    }
    CP_COMMIT();
    CP_WAIT(0);
    __syncthreads();

    uint32_t qh[8][4];
    {
        const uint32_t qa = uSt + (uint32_t)(wid * 16 + (lane & 15)) * SRB
                          + (lane >> 4) * 16;
        #pragma unroll
        for (int dc = 0; dc < 8; dc++)
            LDSM4(qh[dc], qa + dc * 32);
    }
    __syncthreads();   // stage area free for KV

    // paired ldmatrix lane offsets
    const uint32_t kOff = (uint32_t)((lane >> 4) * 8 + (lane & 7)) * SRB
                        + ((lane >> 3) & 1) * 16;
    const uint32_t vOff = (uint32_t)(((lane >> 3) & 1) * 8 + (lane & 7)) * SRB
                        + ((lane >> 4) & 1) * 16;

    float o[16][4];
    #pragma unroll
    for (int i = 0; i < 16; i++)
        #pragma unroll
        for (int j = 0; j < 4; j++) o[i][j] = 0.f;
    float m0 = -1e30f, m1 = -1e30f, l0 = 0.f, l1 = 0.f;

    // preload tile 0
    #pragma unroll
    for (int i = 0; i < 4; i++) {
        int c = tid + 256 * i;
        int row = c >> 4, c16 = c & 15;
        size_t go = (size_t)row * (KH * HD) + c16 * 8;
        CP16(uSt + (uint32_t)row * SRB + c16 * 16, Kg + go);
        CP16(uSt + 64 * SRB + (uint32_t)row * SRB + c16 * 16, Vg + go);
    }
    CP_COMMIT();

    for (int t = 0; t < ntiles; t++) {
        CP_WAIT(0);
        __syncthreads();                 // tile t visible; all done reading other stage

        if (t + 1 < ntiles) {
            uint32_t st = uSt + ((t + 1) & 1) * (2 * 64 * SRB);
            const int s0 = (t + 1) * 64;
            #pragma unroll
            for (int i = 0; i < 4; i++) {
                int c = tid + 256 * i;
                int row = c >> 4, c16 = c & 15;
                size_t go = (size_t)(s0 + row) * (KH * HD) + c16 * 8;
                CP16(st + (uint32_t)row * SRB + c16 * 16, Kg + go);
                CP16(st + 64 * SRB + (uint32_t)row * SRB + c16 * 16, Vg + go);
            }
            CP_COMMIT();
        }

        const uint32_t uK = uSt + (t & 1) * (2 * 64 * SRB);
        const uint32_t uV = uK + 64 * SRB;

        // ---- S = Q K^T ----  (paired x4 non-trans K loads, single Q term)
        float s[8][4];
        #pragma unroll
        for (int nt = 0; nt < 8; nt++)
            #pragma unroll
            for (int j = 0; j < 4; j++) s[nt][j] = 0.f;

        #pragma unroll
        for (int dc = 0; dc < 8; dc++) {
            #pragma unroll
            for (int ntp = 0; ntp < 4; ntp++) {
                uint32_t r[4];
                LDSM4(r, uK + kOff + (uint32_t)ntp * 16 * SRB + dc * 32);
                uint32_t b0[2] = {r[0], r[1]}, b1[2] = {r[2], r[3]};
                MMAH(s[2*ntp],     qh[dc], b0);
                MMAH(s[2*ntp + 1], qh[dc], b1);
            }
        }

        // ---- causal mask ----
        if (t >= 2 * qi) {
            const int r0 = tq0 + wid * 16 + (lane >> 2);
            const int cB = t * 64 + (lane & 3) * 2;
            #pragma unroll
            for (int nt = 0; nt < 8; nt++) {
                int c0 = cB + nt * 8;
                if (c0     > r0)     s[nt][0] = -1e30f;
                if (c0 + 1 > r0)     s[nt][1] = -1e30f;
                if (c0     > r0 + 8) s[nt][2] = -1e30f;
                if (c0 + 1 > r0 + 8) s[nt][3] = -1e30f;
            }
        }

        // ---- online softmax ----
        float mr0 = -1e30f, mr1 = -1e30f;
        #pragma unroll
        for (int nt = 0; nt < 8; nt++) {
            mr0 = fmaxf(mr0, fmaxf(s[nt][0], s[nt][1]));
            mr1 = fmaxf(mr1, fmaxf(s[nt][2], s[nt][3]));
        }
        mr0 = fmaxf(mr0, __shfl_xor_sync(0xffffffffu, mr0, 1));
        mr0 = fmaxf(mr0, __shfl_xor_sync(0xffffffffu, mr0, 2));
        mr1 = fmaxf(mr1, __shfl_xor_sync(0xffffffffu, mr1, 1));
        mr1 = fmaxf(mr1, __shfl_xor_sync(0xffffffffu, mr1, 2));

        const float mn0 = fmaxf(m0, mr0), mn1 = fmaxf(m1, mr1);
        const float a0 = __expf(m0 - mn0), a1 = __expf(m1 - mn1);
        m0 = mn0; m1 = mn1;

        float ls0 = 0.f, ls1 = 0.f;
        #pragma unroll
        for (int nt = 0; nt < 8; nt++) {
            s[nt][0] = __expf(s[nt][0] - m0); ls0 += s[nt][0];
            s[nt][1] = __expf(s[nt][1] - m0); ls0 += s[nt][1];
            s[nt][2] = __expf(s[nt][2] - m1); ls1 += s[nt][2];
            s[nt][3] = __expf(s[nt][3] - m1); ls1 += s[nt][3];
        }
        ls0 += __shfl_xor_sync(0xffffffffu, ls0, 1);
        ls0 += __shfl_xor_sync(0xffffffffu, ls0, 2);
        ls1 += __shfl_xor_sync(0xffffffffu, ls1, 1);
        ls1 += __shfl_xor_sync(0xffffffffu, ls1, 2);
        l0 = l0 * a0 + ls0;
        l1 = l1 * a1 + ls1;

        #pragma unroll
        for (int i = 0; i < 16; i++) {
            o[i][0] *= a0; o[i][1] *= a0; o[i][2] *= a1; o[i][3] *= a1;
        }

        // ---- P fragments (single fp16) ----
        uint32_t phi[4][4];
        #pragma unroll
        for (int kc = 0; kc < 4; kc++) {
            #pragma unroll
            for (int q = 0; q < 4; q++) {
                int nt = 2 * kc + (q >> 1);
                __half2 h = __floats2half2_rn(s[nt][(q & 1) * 2],
                                              s[nt][(q & 1) * 2 + 1]);
                phi[kc][q] = *(uint32_t*)&h;
            }
        }

        // ---- O += P V ----  (paired x4 trans V loads, single P term)
        #pragma unroll
        for (int np = 0; np < 8; np++) {
            #pragma unroll
            for (int kc = 0; kc < 4; kc++) {
                uint32_t r[4];
                LDSM4T(r, uV + vOff + (uint32_t)kc * 16 * SRB + np * 32);
                uint32_t b0[2] = {r[0], r[1]}, b1[2] = {r[2], r[3]};
                MMAH(o[2*np],     phi[kc], b0);
                MMAH(o[2*np + 1], phi[kc], b1);
            }
        }
    }

    // ---- epilogue: O / l, write single fp16 ----
    const float i0 = 1.f / l0, i1 = 1.f / l1;
    const int r0 = tq0 + wid * 16 + (lane >> 2);
    const int cofs = (lane & 3) * 2;
    #pragma unroll
    for (int nt2 = 0; nt2 < 16; nt2++) {
        float v0 = o[nt2][0] * i0, v1 = o[nt2][1] * i0;
        float v2 = o[nt2][2] * i1, v3 = o[nt2][3] * i1;
        size_t p0 = ((size_t)r0 * NH + n) * HD + nt2 * 8 + cofs;
        size_t p1 = ((size_t)(r0 + 8) * NH + n) * HD + nt2 * 8 + cofs;
        *(__half2*)(Oh + p0) = __floats2half2_rn(v0, v1);
        *(__half2*)(Oh + p1) = __floats2half2_rn(v2, v3);
    }
}

// ====================== launch ======================
extern "C" void kernel_launch(void* const* d_in, const int* in_sizes, int n_in,
                              void* d_out, int out_size)
{
    const float* x   = (const float*)d_in[0];
    const int*   pos = (const int*)  d_in[1];
    const float* w_q = (const float*)d_in[2];
    const float* w_k = (const float*)d_in[3];
    const float* w_v = (const float*)d_in[4];
    const float* w_o = (const float*)d_in[5];
    float* out = (float*)d_out;

    float *q, *k;
    cudaGetSymbolAddress((void**)&q, g_q);
    cudaGetSymbolAddress((void**)&k, g_k);
    __half *xh, *aoh, *wqT, *wkT, *wvT, *woT, *qh, *kh, *vh;
    cudaGetSymbolAddress((void**)&xh,  g_xh);
    cudaGetSymbolAddress((void**)&aoh, g_aoh);
    cudaGetSymbolAddress((void**)&wqT, g_wqT); cudaGetSymbolAddress((void**)&wkT, g_wkT);
    cudaGetSymbolAddress((void**)&wvT, g_wvT); cudaGetSymbolAddress((void**)&woT, g_woT);
    cudaGetSymbolAddress((void**)&qh,  g_qh);
    cudaGetSymbolAddress((void**)&kh,  g_kh);  cudaGetSymbolAddress((void**)&vh,  g_vh);

    cudaFuncSetAttribute(gemm_qkv, cudaFuncAttributeMaxDynamicSharedMemorySize, GEMM_SMEM);
    cudaFuncSetAttribute(gemm_o,   cudaFuncAttributeMaxDynamicSharedMemorySize, GEMM_SMEM);
    cudaFuncSetAttribute(flash_h,  cudaFuncAttributeMaxDynamicSharedMemorySize, FL_SMEM);

    // operand prep (ordered so the 5th launch is the merged QKV GEMM for ncu -s 5)
    conv_h<<<(TT*DD/4 + 255)/256, 256>>>(x, xh, TT*DD/4);
    transT_f16<<<dim3(DD/32, DD/32),    256>>>(w_q, wqT, DD, DD);
    transT_f16<<<dim3(KH*HD/32, DD/32), 256>>>(w_k, wkT, DD, KH*HD);
    transT_f16<<<dim3(KH*HD/32, DD/32), 256>>>(w_v, wvT, DD, KH*HD);

    // merged QKV projection (all single-term)
    gemm_qkv<<<dim3(48, 16), 256, GEMM_SMEM>>>(xh, wqT, wkT, wvT, q, k, vh);

    transT_f16<<<dim3(DD/32, DD/32),    256>>>(w_o, woT, DD, DD);

    // RoPE -> single fp16
    rope_h<<<(TT*NH*64 + 255)/256, 256>>>(q, pos, qh, NH, SCALE);
    rope_h<<<(TT*KH*64 + 255)/256, 256>>>(k, pos, kh, KH, 1.0f);

    // causal GQA flash attention (HMMA, all single fp16)
    flash_h<<<dim3(TT/128, NH), 256, FL_SMEM>>>(qh, kh, vh, aoh);

    // output projection (single-term)
    gemm_o<<<dim3(32, 16), 256, GEMM_SMEM>>>(aoh, woT, out);
}

// round 12
// speedup vs baseline: 2.0544x; 1.1447x over previous
#include <cuda_runtime.h>
#include <cuda_fp16.h>
#include <cstdint>
#include <math.h>

// Problem constants
#define TT 2048
#define DD 4096
#define NH 32
#define KH 8
#define HD 128
#define SCALE 0.08838834764831843f   // 1/sqrt(128)

// ====================== PTX helpers (base sm_103-legal only) ======================
__device__ __forceinline__ uint32_t smem_to_u32(const void* p) {
    uint32_t a;
    asm("{ .reg .u64 t; cvta.to.shared.u64 t, %1; cvt.u32.u64 %0, t; }" : "=r"(a) : "l"(p));
    return a;
}
#define CP16(sa, ga) \
    asm volatile("cp.async.cg.shared.global [%0], [%1], 16;" :: "r"(sa), "l"(ga) : "memory")
#define CP_COMMIT() asm volatile("cp.async.commit_group;" ::: "memory")
#define CP_WAIT(n)  asm volatile("cp.async.wait_group %0;" :: "n"(n) : "memory")
#define LDSM4(r, a) \
    asm volatile("ldmatrix.sync.aligned.m8n8.x4.shared.b16 {%0,%1,%2,%3}, [%4];" \
        : "=r"((r)[0]), "=r"((r)[1]), "=r"((r)[2]), "=r"((r)[3]) : "r"(a))
#define LDSM4T(r, a) \
    asm volatile("ldmatrix.sync.aligned.m8n8.x4.trans.shared.b16 {%0,%1,%2,%3}, [%4];" \
        : "=r"((r)[0]), "=r"((r)[1]), "=r"((r)[2]), "=r"((r)[3]) : "r"(a))
#define MMAH(d, a, b) \
    asm volatile("mma.sync.aligned.m16n8k16.row.col.f32.f16.f16.f32 " \
        "{%0,%1,%2,%3}, {%4,%5,%6,%7}, {%8,%9}, {%0,%1,%2,%3};" \
        : "+f"((d)[0]), "+f"((d)[1]), "+f"((d)[2]), "+f"((d)[3]) \
        : "r"((a)[0]), "r"((a)[1]), "r"((a)[2]), "r"((a)[3]), "r"((b)[0]), "r"((b)[1]))

// ====================== device scratch ======================
__device__ __half g_xh  [TT * DD];
__device__ __half g_aoh [TT * DD];
__device__ __half g_wq16[DD * DD];       // fp16 copy, natural [K,N] layout
__device__ __half g_wk16[DD * KH*HD];
__device__ __half g_wv16[DD * KH*HD];
__device__ __half g_wo16[DD * DD];
__device__ __half g_qh  [TT * NH * HD];
__device__ __half g_kh  [TT * KH * HD];
__device__ __half g_vh  [TT * KH * HD];

// ====================== fp32 -> fp16 convert ======================
__global__ void conv_h(const float* __restrict__ s, __half* __restrict__ d, int n4)
{
    int i = blockIdx.x * 256 + threadIdx.x;
    if (i >= n4) return;
    float4 f = ((const float4*)s)[i];
    __align__(8) __half h[4] = {__float2half_rn(f.x), __float2half_rn(f.y),
                                __float2half_rn(f.z), __float2half_rn(f.w)};
    *(uint2*)(d + 4 * (size_t)i) = *(uint2*)h;
}

// ====================== mma.sync GEMM core ======================
// 128x128 CTA tile, BK=32, 8 warps (2x4), warp tile 64x32, 3-stage, 1 barrier/stage.
// A smem [M,K] (non-trans frags).  B smem [K,N] (trans frags, flash-PV pattern).
#define SRA 80                         // A row stride bytes (32 halves + pad)
#define SRB2 272                       // B row stride bytes (128 halves + pad)
#define A_TILE (128 * SRA)             // 10240
#define B_TILE (32 * SRB2)             // 8704
#define STAGE_B (A_TILE + B_TILE)      // 18944
#define GEMM_SMEM (3 * STAGE_B)        // 56832
#define QKV_SMEM 66560                 // max(GEMM_SMEM, 128*130*4 epilogue stage)

struct AccT { float a[4][4][4]; };

__device__ __forceinline__ void gemm_core(
    uint32_t sbase, const __half* pA, const __half* pB, int Kd, int Nw, AccT& A)
{
    const int tid = threadIdx.x, lane = tid & 31, wid = tid >> 5;
    const int wm = wid >> 2, wn = wid & 3;
    const int arow = tid >> 2;             // 0..63 (+64)
    const uint32_t aso = (tid & 3) * 16;
    const int acol = (tid & 3) * 8;
    const int brow = tid >> 4;             // 0..15 (+16)
    const int bc16 = tid & 15;

    const int nst = Kd >> 5;

    #pragma unroll
    for (int ps = 0; ps < 2; ps++) {       // prologue stages 0,1
        const int k0 = ps << 5;
        uint32_t st = sbase + ps * STAGE_B;
        #pragma unroll
        for (int i = 0; i < 2; i++) {
            int row = arow + 64 * i;
            CP16(st + (uint32_t)row * SRA + aso, pA + (size_t)row * Kd + k0 + acol);
        }
        #pragma unroll
        for (int i = 0; i < 2; i++) {
            int row = brow + 16 * i;
            CP16(st + A_TILE + (uint32_t)row * SRB2 + bc16 * 16,
                 pB + (size_t)(k0 + row) * Nw + bc16 * 8);
        }
        CP_COMMIT();
    }

    int sidx = 0;
    for (int s = 0; s < nst; s++) {
        if (s + 1 < nst) { CP_WAIT(1); } else { CP_WAIT(0); }
        __syncthreads();                   // single barrier per stage

        if (s + 2 < nst) {
            const int k0 = (s + 2) << 5;
            int lidx = sidx - 1; if (lidx < 0) lidx += 3;
            uint32_t st = sbase + lidx * STAGE_B;
            #pragma unroll
            for (int i = 0; i < 2; i++) {
                int row = arow + 64 * i;
                CP16(st + (uint32_t)row * SRA + aso, pA + (size_t)row * Kd + k0 + acol);
            }
            #pragma unroll
            for (int i = 0; i < 2; i++) {
                int row = brow + 16 * i;
                CP16(st + A_TILE + (uint32_t)row * SRB2 + bc16 * 16,
                     pB + (size_t)(k0 + row) * Nw + bc16 * 8);
            }
            CP_COMMIT();
        }

        uint32_t st = sbase + sidx * STAGE_B;
        const uint32_t aAddr = st + (uint32_t)(wm * 64 + (lane & 15)) * SRA
                             + (lane >> 4) * 16;
        const uint32_t bAddr = st + A_TILE
                             + (uint32_t)(((lane >> 3) & 1) * 8 + (lane & 7)) * SRB2
                             + ((lane >> 4) & 1) * 16 + wn * 64;

        #pragma unroll
        for (int kk = 0; kk < 2; kk++) {
            uint32_t ah[4][4], bb[4][2];
            #pragma unroll
            for (int mt = 0; mt < 4; mt++)
                LDSM4(ah[mt], aAddr + mt * 16 * SRA + kk * 32);
            #pragma unroll
            for (int np = 0; np < 2; np++) {
                uint32_t r[4];
                LDSM4T(r, bAddr + kk * 16 * SRB2 + np * 32);
                bb[2*np][0] = r[0]; bb[2*np][1] = r[1];
                bb[2*np+1][0] = r[2]; bb[2*np+1][1] = r[3];
            }
            #pragma unroll
            for (int mt = 0; mt < 4; mt++)
                #pragma unroll
                for (int nt = 0; nt < 4; nt++)
                    MMAH(A.a[mt][nt], ah[mt], bb[nt]);
        }
        if (++sidx == 3) sidx = 0;
    }
}

// ---- merged QKV projection + fused RoPE: grid (48, 16) ----
__global__ __launch_bounds__(256) void gemm_qkv(
    const __half* __restrict__ Ah,
    const __half* __restrict__ WQ, const __half* __restrict__ WK,
    const __half* __restrict__ WV, const int* __restrict__ pos,
    __half* __restrict__ Qh, __half* __restrict__ Kh, __half* __restrict__ Vh)
{
    extern __shared__ char smraw[];
    const uint32_t sbase = smem_to_u32(smraw);
    const int bx = blockIdx.x;
    const int Kd = DD;

    const __half* pB;
    int bn, kind, Nw;   // kind 0=q(rope), 1=k(rope), 2=v(fp16 direct)
    if (bx < 32)      { pB = WQ; bn = bx;      kind = 0; Nw = NH * HD; }
    else if (bx < 40) { pB = WK; bn = bx - 32; kind = 1; Nw = KH * HD; }
    else              { pB = WV; bn = bx - 40; kind = 2; Nw = KH * HD; }
    pB += (size_t)bn * 128;

    AccT A;
    #pragma unroll
    for (int mt = 0; mt < 4; mt++)
        #pragma unroll
        for (int nt = 0; nt < 4; nt++)
            #pragma unroll
            for (int q = 0; q < 4; q++) A.a[mt][nt][q] = 0.f;

    gemm_core(sbase, Ah + (size_t)blockIdx.y * 128 * Kd, pB, Kd, Nw, A);

    const int tid = threadIdx.x;
    const int lane = tid & 31, wid = tid >> 5;
    const int wm = wid >> 2, wn = wid & 3;

    if (kind == 2) {
        const int rb = blockIdx.y * 128 + wm * 64 + (lane >> 2);
        const int cbl = bn * 128 + wn * 32 + (lane & 3) * 2;
        #pragma unroll
        for (int mt = 0; mt < 4; mt++)
            #pragma unroll
            for (int nt = 0; nt < 4; nt++) {
                const int row = rb + mt * 16;
                const int col = cbl + nt * 8;
                *(__half2*)(Vh + (size_t)row * (KH*HD) + col) =
                    __floats2half2_rn(A.a[mt][nt][0], A.a[mt][nt][1]);
                *(__half2*)(Vh + (size_t)(row + 8) * (KH*HD) + col) =
                    __floats2half2_rn(A.a[mt][nt][2], A.a[mt][nt][3]);
            }
        return;
    }

    // ---- fused RoPE: stage fp32 tile in smem, rotate pairs (c, c+64) ----
    __syncthreads();                   // all warps done reading stage smem
    float* sm = (float*)smraw;         // [128][130]
    #pragma unroll
    for (int mt = 0; mt < 4; mt++)
        #pragma unroll
        for (int nt = 0; nt < 4; nt++) {
            const int rl = wm * 64 + mt * 16 + (lane >> 2);
            const int cl = wn * 32 + (lane & 3) * 2 + nt * 8;
            *(float2*)&sm[rl * 130 + cl] = make_float2(A.a[mt][nt][0], A.a[mt][nt][1]);
            *(float2*)&sm[(rl + 8) * 130 + cl] = make_float2(A.a[mt][nt][2], A.a[mt][nt][3]);
        }
    __syncthreads();

    const float scale = (kind == 0) ? SCALE : 1.0f;
    __half* dst = (kind == 0) ? Qh : Kh;
    const int HEADS = (kind == 0) ? NH : KH;
    const int c = tid & 63;
    const int rbase = tid >> 6;        // 0..3
    const float e = (float)c * (1.0f / 64.0f);
    const float invf = 1.0f / powf(10000.0f, e);

    #pragma unroll 4
    for (int i = 0; i < 32; i++) {
        const int row = i * 4 + rbase;
        const int t = blockIdx.y * 128 + row;
        float sn, cs;
        sincosf((float)pos[t] * invf, &sn, &cs);
        const float x1 = sm[row * 130 + c];
        const float x2 = sm[row * 130 + c + 64];
        const size_t o = ((size_t)t * HEADS + bn) * HD + c;
        dst[o]      = __float2half_rn((x1 * cs - x2 * sn) * scale);
        dst[o + 64] = __float2half_rn((x2 * cs + x1 * sn) * scale);
    }
}

// ---- o-proj: C fp32, grid (32, 16) ----
__global__ __launch_bounds__(256) void gemm_o(
    const __half* __restrict__ Ah, const __half* __restrict__ B,
    float* __restrict__ C)
{
    extern __shared__ char smraw[];
    const uint32_t sbase = smem_to_u32(smraw);
    const int Kd = DD, N = DD;

    AccT A;
    #pragma unroll
    for (int mt = 0; mt < 4; mt++)
        #pragma unroll
        for (int nt = 0; nt < 4; nt++)
            #pragma unroll
            for (int q = 0; q < 4; q++) A.a[mt][nt][q] = 0.f;

    gemm_core(sbase, Ah + (size_t)blockIdx.y * 128 * Kd,
              B + (size_t)blockIdx.x * 128, Kd, N, A);

    const int lane = threadIdx.x & 31, wid = threadIdx.x >> 5;
    const int wm = wid >> 2, wn = wid & 3;
    const int rb = blockIdx.y * 128 + wm * 64 + (lane >> 2);
    const int cb = blockIdx.x * 128 + wn * 32 + (lane & 3) * 2;
    #pragma unroll
    for (int mt = 0; mt < 4; mt++)
        #pragma unroll
        for (int nt = 0; nt < 4; nt++) {
            const int row = rb + mt * 16;
            const int col = cb + nt * 8;
            *(float2*)(C + (size_t)row * N + col) =
                make_float2(A.a[mt][nt][0], A.a[mt][nt][1]);
            *(float2*)(C + (size_t)(row + 8) * N + col) =
                make_float2(A.a[mt][nt][2], A.a[mt][nt][3]);
        }
}

// ====================== HMMA flash attention (causal, GQA) ======================
// CTA: 128 q rows x 1 head, 8 warps (16 q rows each). KV tiles of 64.
#define SRH 136
#define SRB 272
#define FL_SMEM ((4 * 64 * SRH) * 2)   // 2 stages of (K,V) = 69632

__global__ __launch_bounds__(256) void flash_h(
    const __half* __restrict__ Qv, const __half* __restrict__ Kv,
    const __half* __restrict__ Vv, __half* __restrict__ Oh)
{
    extern __shared__ char fsm[];
    const uint32_t uSt = smem_to_u32(fsm);

    const int tid = threadIdx.x, lane = tid & 31, wid = tid >> 5;
    const int qi = gridDim.x - 1 - blockIdx.x;     // heavy tiles first
    const int n = blockIdx.y, kvh = n >> 2;
    const int tq0 = qi * 128;
    const int ntiles = 2 * qi + 2;

    const __half* Qg = Qv + ((size_t)tq0 * NH + n) * HD;
    const __half* Kg = Kv + (size_t)kvh * HD;
    const __half* Vg = Vv + (size_t)kvh * HD;

    // ---- stage Q into stage-0 area, read frags ----
    #pragma unroll
    for (int i = 0; i < 8; i++) {
        int c = tid + 256 * i;
        int row = c >> 4, c16 = c & 15;
        CP16(uSt + (uint32_t)row * SRB + c16 * 16,
             Qg + (size_t)row * (NH * HD) + c16 * 8);
    }
    CP_COMMIT();
    CP_WAIT(0);
    __syncthreads();

    uint32_t qh[8][4];
    {
        const uint32_t qa = uSt + (uint32_t)(wid * 16 + (lane & 15)) * SRB
                          + (lane >> 4) * 16;
        #pragma unroll
        for (int dc = 0; dc < 8; dc++)
            LDSM4(qh[dc], qa + dc * 32);
    }
    __syncthreads();   // stage area free for KV

    // paired ldmatrix lane offsets
    const uint32_t kOff = (uint32_t)((lane >> 4) * 8 + (lane & 7)) * SRB
                        + ((lane >> 3) & 1) * 16;
    const uint32_t vOff = (uint32_t)(((lane >> 3) & 1) * 8 + (lane & 7)) * SRB
                        + ((lane >> 4) & 1) * 16;

    float o[16][4];
    #pragma unroll
    for (int i = 0; i < 16; i++)
        #pragma unroll
        for (int j = 0; j < 4; j++) o[i][j] = 0.f;
    float m0 = -1e30f, m1 = -1e30f, l0 = 0.f, l1 = 0.f;

    // preload tile 0
    #pragma unroll
    for (int i = 0; i < 4; i++) {
        int c = tid + 256 * i;
        int row = c >> 4, c16 = c & 15;
        size_t go = (size_t)row * (KH * HD) + c16 * 8;
        CP16(uSt + (uint32_t)row * SRB + c16 * 16, Kg + go);
        CP16(uSt + 64 * SRB + (uint32_t)row * SRB + c16 * 16, Vg + go);
    }
    CP_COMMIT();

    for (int t = 0; t < ntiles; t++) {
        CP_WAIT(0);
        __syncthreads();                 // tile t visible; all done reading other stage

        if (t + 1 < ntiles) {
            uint32_t st = uSt + ((t + 1) & 1) * (2 * 64 * SRB);
            const int s0 = (t + 1) * 64;
            #pragma unroll
            for (int i = 0; i < 4; i++) {
                int c = tid + 256 * i;
                int row = c >> 4, c16 = c & 15;
                size_t go = (size_t)(s0 + row) * (KH * HD) + c16 * 8;
                CP16(st + (uint32_t)row * SRB + c16 * 16, Kg + go);
                CP16(st + 64 * SRB + (uint32_t)row * SRB + c16 * 16, Vg + go);
            }
            CP_COMMIT();
        }

        const uint32_t uK = uSt + (t & 1) * (2 * 64 * SRB);
        const uint32_t uV = uK + 64 * SRB;

        // ---- S = Q K^T ----
        float s[8][4];
        #pragma unroll
        for (int nt = 0; nt < 8; nt++)
            #pragma unroll
            for (int j = 0; j < 4; j++) s[nt][j] = 0.f;

        #pragma unroll
        for (int dc = 0; dc < 8; dc++) {
            #pragma unroll
            for (int ntp = 0; ntp < 4; ntp++) {
                uint32_t r[4];
                LDSM4(r, uK + kOff + (uint32_t)ntp * 16 * SRB + dc * 32);
                uint32_t b0[2] = {r[0], r[1]}, b1[2] = {r[2], r[3]};
                MMAH(s[2*ntp],     qh[dc], b0);
                MMAH(s[2*ntp + 1], qh[dc], b1);
            }
        }

        // ---- causal mask ----
        if (t >= 2 * qi) {
            const int r0 = tq0 + wid * 16 + (lane >> 2);
            const int cB = t * 64 + (lane & 3) * 2;
            #pragma unroll
            for (int nt = 0; nt < 8; nt++) {
                int c0 = cB + nt * 8;
                if (c0     > r0)     s[nt][0] = -1e30f;
                if (c0 + 1 > r0)     s[nt][1] = -1e30f;
                if (c0     > r0 + 8) s[nt][2] = -1e30f;
                if (c0 + 1 > r0 + 8) s[nt][3] = -1e30f;
            }
        }

        // ---- online softmax ----
        float mr0 = -1e30f, mr1 = -1e30f;
        #pragma unroll
        for (int nt = 0; nt < 8; nt++) {
            mr0 = fmaxf(mr0, fmaxf(s[nt][0], s[nt][1]));
            mr1 = fmaxf(mr1, fmaxf(s[nt][2], s[nt][3]));
        }
        mr0 = fmaxf(mr0, __shfl_xor_sync(0xffffffffu, mr0, 1));
        mr0 = fmaxf(mr0, __shfl_xor_sync(0xffffffffu, mr0, 2));
        mr1 = fmaxf(mr1, __shfl_xor_sync(0xffffffffu, mr1, 1));
        mr1 = fmaxf(mr1, __shfl_xor_sync(0xffffffffu, mr1, 2));

        const float mn0 = fmaxf(m0, mr0), mn1 = fmaxf(m1, mr1);
        const float a0 = __expf(m0 - mn0), a1 = __expf(m1 - mn1);
        m0 = mn0; m1 = mn1;

        float ls0 = 0.f, ls1 = 0.f;
        #pragma unroll
        for (int nt = 0; nt < 8; nt++) {
            s[nt][0] = __expf(s[nt][0] - m0); ls0 += s[nt][0];
            s[nt][1] = __expf(s[nt][1] - m0); ls0 += s[nt][1];
            s[nt][2] = __expf(s[nt][2] - m1); ls1 += s[nt][2];
            s[nt][3] = __expf(s[nt][3] - m1); ls1 += s[nt][3];
        }
        ls0 += __shfl_xor_sync(0xffffffffu, ls0, 1);
        ls0 += __shfl_xor_sync(0xffffffffu, ls0, 2);
        ls1 += __shfl_xor_sync(0xffffffffu, ls1, 1);
        ls1 += __shfl_xor_sync(0xffffffffu, ls1, 2);
        l0 = l0 * a0 + ls0;
        l1 = l1 * a1 + ls1;

        #pragma unroll
        for (int i = 0; i < 16; i++) {
            o[i][0] *= a0; o[i][1] *= a0; o[i][2] *= a1; o[i][3] *= a1;
        }

        // ---- P fragments (single fp16) ----
        uint32_t phi[4][4];
        #pragma unroll
        for (int kc = 0; kc < 4; kc++) {
            #pragma unroll
            for (int q = 0; q < 4; q++) {
                int nt = 2 * kc + (q >> 1);
                __half2 h = __floats2half2_rn(s[nt][(q & 1) * 2],
                                              s[nt][(q & 1) * 2 + 1]);
                phi[kc][q] = *(uint32_t*)&h;
            }
        }

        // ---- O += P V ----
        #pragma unroll
        for (int np = 0; np < 8; np++) {
            #pragma unroll
            for (int kc = 0; kc < 4; kc++) {
                uint32_t r[4];
                LDSM4T(r, uV + vOff + (uint32_t)kc * 16 * SRB + np * 32);
                uint32_t b0[2] = {r[0], r[1]}, b1[2] = {r[2], r[3]};
                MMAH(o[2*np],     phi[kc], b0);
                MMAH(o[2*np + 1], phi[kc], b1);
            }
        }
    }

    // ---- epilogue: O / l, write single fp16 ----
    const float i0 = 1.f / l0, i1 = 1.f / l1;
    const int r0 = tq0 + wid * 16 + (lane >> 2);
    const int cofs = (lane & 3) * 2;
    #pragma unroll
    for (int nt2 = 0; nt2 < 16; nt2++) {
        float v0 = o[nt2][0] * i0, v1 = o[nt2][1] * i0;
        float v2 = o[nt2][2] * i1, v3 = o[nt2][3] * i1;
        size_t p0 = ((size_t)r0 * NH + n) * HD + nt2 * 8 + cofs;
        size_t p1 = ((size_t)(r0 + 8) * NH + n) * HD + nt2 * 8 + cofs;
        *(__half2*)(Oh + p0) = __floats2half2_rn(v0, v1);
        *(__half2*)(Oh + p1) = __floats2half2_rn(v2, v3);
    }
}

// ====================== launch ======================
extern "C" void kernel_launch(void* const* d_in, const int* in_sizes, int n_in,
                              void* d_out, int out_size)
{
    const float* x   = (const float*)d_in[0];
    const int*   pos = (const int*)  d_in[1];
    const float* w_q = (const float*)d_in[2];
    const float* w_k = (const float*)d_in[3];
    const float* w_v = (const float*)d_in[4];
    const float* w_o = (const float*)d_in[5];
    float* out = (float*)d_out;

    __half *xh, *aoh, *wq16, *wk16, *wv16, *wo16, *qh, *kh, *vh;
    cudaGetSymbolAddress((void**)&xh,   g_xh);
    cudaGetSymbolAddress((void**)&aoh,  g_aoh);
    cudaGetSymbolAddress((void**)&wq16, g_wq16); cudaGetSymbolAddress((void**)&wk16, g_wk16);
    cudaGetSymbolAddress((void**)&wv16, g_wv16); cudaGetSymbolAddress((void**)&wo16, g_wo16);
    cudaGetSymbolAddress((void**)&qh,   g_qh);
    cudaGetSymbolAddress((void**)&kh,   g_kh);   cudaGetSymbolAddress((void**)&vh,   g_vh);

    cudaFuncSetAttribute(gemm_qkv, cudaFuncAttributeMaxDynamicSharedMemorySize, QKV_SMEM);
    cudaFuncSetAttribute(gemm_o,   cudaFuncAttributeMaxDynamicSharedMemorySize, GEMM_SMEM);
    cudaFuncSetAttribute(flash_h,  cudaFuncAttributeMaxDynamicSharedMemorySize, FL_SMEM);

    // fp16 copies (weights already [K,N] naturally)
    conv_h<<<(TT*DD/4 + 255)/256, 256>>>(x,   xh,   TT*DD/4);
    conv_h<<<(DD*DD/4 + 255)/256, 256>>>(w_q, wq16, DD*DD/4);
    conv_h<<<(DD*KH*HD/4 + 255)/256, 256>>>(w_k, wk16, DD*KH*HD/4);
    conv_h<<<(DD*KH*HD/4 + 255)/256, 256>>>(w_v, wv16, DD*KH*HD/4);

    // merged QKV projection + fused RoPE
    gemm_qkv<<<dim3(48, 16), 256, QKV_SMEM>>>(xh, wq16, wk16, wv16, pos, qh, kh, vh);

    conv_h<<<(DD*DD/4 + 255)/256, 256>>>(w_o, wo16, DD*DD/4);

    // causal GQA flash attention (HMMA, all single fp16)
    flash_h<<<dim3(TT/128, NH), 256, FL_SMEM>>>(qh, kh, vh, aoh);

    // output projection
    gemm_o<<<dim3(32, 16), 256, GEMM_SMEM>>>(aoh, wo16, out);
}